// round 11
// baseline (speedup 1.0000x reference)
#include <cuda_runtime.h>
#include <cuda_fp16.h>
#include <cstdint>

#define NU 200000
#define NM 100000
#define ND 20000
#define ALPHA 0.01f

#define T0_TILES 3125              // ceil(NU/64)
#define T1_TILES 1563              // ceil(NM/64)
#define T2_TILES 313               // ceil(ND/64)
#define TB1 T0_TILES
#define TB2 (T0_TILES + T1_TILES)
#define TT  (T0_TILES + T1_TILES + T2_TILES)   // 5001

// ---------------- persistent device scratch (zero-initialized at load) ----------------
__device__ float d_gu[NU * 16];
__device__ float d_gm[NM * 16];
__device__ float d_gd[ND * 16];
__device__ float d_au[NU * 16];   // raw-sum buffers: zero at entry/exit invariant
__device__ float d_ad[ND * 16];
__device__ float d_sr[NM * 16];   // movie sums from 'rates'
__device__ float d_sdi[NM * 16];  // movie sums from 'dir'
__device__ int   d_deg_r[NM];     // degree counters: zero at entry/exit invariant
__device__ int   d_deg_di[NM];
__device__ int   d_deg_rb[NU];
__device__ int   d_deg_db[ND];
__device__ float d_invr[NM];      // 0.5/deg scales for layer-2 (written by update_all)
__device__ float d_invdi[NM];

// ---------------- helpers ----------------
__device__ __forceinline__ uint32_t smem_u32(const void* p) {
    uint32_t a;
    asm("{ .reg .u64 t; cvta.to.shared.u64 t, %1; cvt.u32.u64 %0, t; }" : "=r"(a) : "l"(p));
    return a;
}
__device__ __forceinline__ void ldmx4(uint32_t& a0, uint32_t& a1, uint32_t& a2, uint32_t& a3,
                                      uint32_t addr) {
    asm volatile("ldmatrix.sync.aligned.m8n8.x4.shared.b16 {%0,%1,%2,%3}, [%4];"
                 : "=r"(a0), "=r"(a1), "=r"(a2), "=r"(a3) : "r"(addr));
}
__device__ __forceinline__ void mma_h(float& c0, float& c1, float& c2, float& c3,
                                      uint32_t a0, uint32_t a1, uint32_t a2, uint32_t a3,
                                      uint32_t b0, uint32_t b1) {
    asm volatile("mma.sync.aligned.m16n8k16.row.col.f32.f16.f16.f32 "
                 "{%0,%1,%2,%3}, {%4,%5,%6,%7}, {%8,%9}, {%0,%1,%2,%3};"
                 : "+f"(c0), "+f"(c1), "+f"(c2), "+f"(c3)
                 : "r"(a0), "r"(a1), "r"(a2), "r"(a3), "r"(b0), "r"(b1));
}
__device__ __forceinline__ uint32_t pack_h2(float x, float y) {
    __half2 h = __floats2half2_rn(x, y);
    return *(uint32_t*)&h;
}
__device__ __forceinline__ void cp16(uint32_t dst, const void* src, int pbytes) {
    asm volatile("cp.async.cg.shared.global [%0], [%1], 16, %2;"
                 :: "r"(dst), "l"(src), "r"(pbytes));
}
#define CP_COMMIT() asm volatile("cp.async.commit_group;" ::: "memory")
#define CP_WAIT0()  asm volatile("cp.async.wait_group 0;" ::: "memory")

// ---------------- persistent fused GEMM over all 3 node types ----------------
// G = relu(X @ W^T + b) @ Wout^T. fp16 hi-only A/B/H/Wout (calibrated ~2.2e-4).
// cp.async double-buffers raw X.
// smem: A[64][136]h @0 (17408) | B[128][136]h @17408 (34816) | RAW f32 @52224 (32768)
//       Pb[4][64][16]f32 (16KB) aliases A after the MMA mainloop.
#define PDA 136
#define OFF_A   0
#define OFF_B   17408
#define OFF_RAW 52224
#define SM_TOTAL 84992
#define GEMM_GRID 296

__global__ void __launch_bounds__(256, 2)
gemm_all(const float4* __restrict__ Xu, const float4* __restrict__ Xm,
         const float4* __restrict__ Xd,
         const float4* __restrict__ Wu, const float4* __restrict__ Wm,
         const float4* __restrict__ Wd,
         const float* __restrict__ bu, const float* __restrict__ bm,
         const float* __restrict__ bd,
         const float* __restrict__ Wout,
         float4* __restrict__ Gu, float4* __restrict__ Gm, float4* __restrict__ Gd) {
    extern __shared__ __align__(16) char smem[];
    const uint32_t sb = smem_u32(smem);
    const int tid = threadIdx.x;
    const int wid = tid >> 5;
    const int lane = tid & 31;

    const int t0 = (int)(((long long)blockIdx.x * TT) / GEMM_GRID);
    const int t1 = (int)(((long long)(blockIdx.x + 1) * TT) / GEMM_GRID);

    const int mw = wid >> 2;
    const int nw = wid & 3;
    const int a_r = (lane & 15);
    const int a_k8 = (lane >> 4) * 8;
    const int b_r = (lane & 7) + ((lane >> 4) << 3);
    const int b_k8 = ((lane >> 3) & 1) * 8;
    const int crow = lane >> 2;
    const int ccol2 = (lane & 3) * 2;
    const int prow = tid >> 2;
    const int jq = tid & 3;

    // ---- Wout B-fragments (fp16 hi) — ONCE ----
    uint32_t wo[2][2][2];
    {
        const int wn = lane >> 2;
#pragma unroll
        for (int kl = 0; kl < 2; kl++)
#pragma unroll
            for (int t = 0; t < 2; t++) {
                const float* wr = Wout + (size_t)(t * 8 + wn) * 128 + nw * 32 + kl * 16;
                wo[kl][t][0] = pack_h2(wr[ccol2], wr[ccol2 + 1]);
                wo[kl][t][1] = pack_h2(wr[8 + ccol2], wr[9 + ccol2]);
            }
    }

    float* Pb = (float*)(smem + OFF_A);
    float2 biasr[4];
    int curtype = -1;

    // ---- preamble: prefetch raw X for first tile ----
    {
        int t = t0;
        int ty = (t >= TB2) ? 2 : (t >= TB1) ? 1 : 0;
        int lt = t - (ty == 2 ? TB2 : ty == 1 ? TB1 : 0);
        const float4* Xp = (ty == 0) ? Xu : (ty == 1) ? Xm : Xd;
        int Nn = (ty == 0) ? NU : (ty == 1) ? NM : ND;
        int row0 = lt * 64;
#pragma unroll
        for (int u = 0; u < 8; u++) {
            int idx = tid + u * 256;
            int row = row0 + (idx >> 5);
            int ok = row < Nn;
            const float4* src = Xp + (size_t)(ok ? row : 0) * 32 + (idx & 31);
            cp16(sb + OFF_RAW + idx * 16, src, ok ? 16 : 0);
        }
        CP_COMMIT();
    }

    for (int t = t0; t < t1; t++) {
        const int ty = (t >= TB2) ? 2 : (t >= TB1) ? 1 : 0;
        const int lt = t - (ty == 2 ? TB2 : ty == 1 ? TB1 : 0);
        const int Nn = (ty == 0) ? NU : (ty == 1) ? NM : ND;
        float4* Gp = (ty == 0) ? Gu : (ty == 1) ? Gm : Gd;
        const int row0 = lt * 64;

        if (ty != curtype) {
            const float4* Wp = (ty == 0) ? Wu : (ty == 1) ? Wm : Wd;
            const float* bp = (ty == 0) ? bu : (ty == 1) ? bm : bd;
#pragma unroll
            for (int u = 0; u < 16; u++) {
                int idx = tid + u * 256;
                int row = idx >> 5, q4 = idx & 31;
                float4 v = Wp[(size_t)row * 32 + q4];
                uint32_t h0 = pack_h2(v.x, v.y);
                uint32_t h1 = pack_h2(v.z, v.w);
                *(uint2*)(smem + OFF_B + (row * PDA + q4 * 4) * 2) = make_uint2(h0, h1);
            }
#pragma unroll
            for (int ni = 0; ni < 4; ni++)
                biasr[ni] = *(const float2*)&bp[nw * 32 + ni * 8 + ccol2];
            curtype = ty;
        }

        CP_WAIT0();
        __syncthreads();                 // raw(t) + B visible

        // ---- convert raw fp32 -> A fp16 (hi only) ----
#pragma unroll
        for (int u = 0; u < 8; u++) {
            int idx = tid + u * 256;
            int row = idx >> 5, q4 = idx & 31;
            float4 v = ((const float4*)(smem + OFF_RAW))[idx];
            uint32_t h0 = pack_h2(v.x, v.y);
            uint32_t h1 = pack_h2(v.z, v.w);
            *(uint2*)(smem + OFF_A + (row * PDA + q4 * 4) * 2) = make_uint2(h0, h1);
        }
        __syncthreads();                 // A ready; raw buffer free

        // ---- prefetch next tile's raw X (overlaps MMA) ----
        if (t + 1 < t1) {
            int tn = t + 1;
            int tyn = (tn >= TB2) ? 2 : (tn >= TB1) ? 1 : 0;
            int ltn = tn - (tyn == 2 ? TB2 : tyn == 1 ? TB1 : 0);
            const float4* Xn = (tyn == 0) ? Xu : (tyn == 1) ? Xm : Xd;
            int Nx = (tyn == 0) ? NU : (tyn == 1) ? NM : ND;
            int r0n = ltn * 64;
#pragma unroll
            for (int u = 0; u < 8; u++) {
                int idx = tid + u * 256;
                int row = r0n + (idx >> 5);
                int ok = row < Nx;
                const float4* src = Xn + (size_t)(ok ? row : 0) * 32 + (idx & 31);
                cp16(sb + OFF_RAW + idx * 16, src, ok ? 16 : 0);
            }
            CP_COMMIT();
        }

        // ---- MMA mainloop: acc = A @ B^T ----
        float acc[2][4][4];
#pragma unroll
        for (int mi = 0; mi < 2; mi++)
#pragma unroll
            for (int ni = 0; ni < 4; ni++)
#pragma unroll
                for (int e = 0; e < 4; e++) acc[mi][ni][e] = 0.0f;

#pragma unroll 2
        for (int k16 = 0; k16 < 8; k16++) {
            const int k0 = k16 * 16;
            uint32_t ah[2][4], bb[2][4];
#pragma unroll
            for (int mi = 0; mi < 2; mi++) {
                int row = mw * 32 + mi * 16 + a_r;
                uint32_t off = (uint32_t)(row * PDA + k0 + a_k8) * 2;
                ldmx4(ah[mi][0], ah[mi][1], ah[mi][2], ah[mi][3], sb + OFF_A + off);
            }
#pragma unroll
            for (int np = 0; np < 2; np++) {
                int row = nw * 32 + np * 16 + b_r;
                uint32_t off = (uint32_t)(row * PDA + k0 + b_k8) * 2;
                ldmx4(bb[np][0], bb[np][1], bb[np][2], bb[np][3], sb + OFF_B + off);
            }
#pragma unroll
            for (int mi = 0; mi < 2; mi++)
#pragma unroll
                for (int ni = 0; ni < 4; ni++) {
                    int np = ni >> 1, half = (ni & 1) * 2;
                    float* c = acc[mi][ni];
                    mma_h(c[0], c[1], c[2], c[3],
                          ah[mi][0], ah[mi][1], ah[mi][2], ah[mi][3],
                          bb[np][half], bb[np][half + 1]);
                }
        }
        __syncthreads();   // A reads done before Pb aliases it

        // ---- bias + relu in regs; tensor-core projection (H hi, Wout hi) ----
        float accP[2][2][4];
#pragma unroll
        for (int mi = 0; mi < 2; mi++)
#pragma unroll
            for (int tt = 0; tt < 2; tt++)
#pragma unroll
                for (int e = 0; e < 4; e++) accP[mi][tt][e] = 0.0f;

#pragma unroll
        for (int mi = 0; mi < 2; mi++) {
#pragma unroll
            for (int ni = 0; ni < 4; ni++) {
                float* c = acc[mi][ni];
                c[0] = fmaxf(c[0] + biasr[ni].x, 0.0f);
                c[1] = fmaxf(c[1] + biasr[ni].y, 0.0f);
                c[2] = fmaxf(c[2] + biasr[ni].x, 0.0f);
                c[3] = fmaxf(c[3] + biasr[ni].y, 0.0f);
            }
#pragma unroll
            for (int kl = 0; kl < 2; kl++) {
                float* L = acc[mi][2 * kl];
                float* R = acc[mi][2 * kl + 1];
                uint32_t a0 = pack_h2(L[0], L[1]);
                uint32_t a1 = pack_h2(L[2], L[3]);
                uint32_t a2 = pack_h2(R[0], R[1]);
                uint32_t a3 = pack_h2(R[2], R[3]);
#pragma unroll
                for (int tt = 0; tt < 2; tt++) {
                    float* p = accP[mi][tt];
                    mma_h(p[0], p[1], p[2], p[3], a0, a1, a2, a3,
                          wo[kl][tt][0], wo[kl][tt][1]);
                }
            }
        }

        // ---- write per-warp partials, k-reduce across the 4 nw warps ----
#pragma unroll
        for (int mi = 0; mi < 2; mi++)
#pragma unroll
            for (int tt = 0; tt < 2; tt++) {
                int R = mw * 32 + mi * 16 + crow;
                int cc = tt * 8 + ccol2;
                *(float2*)&Pb[nw * 1024 + R * 16 + cc] =
                    make_float2(accP[mi][tt][0], accP[mi][tt][1]);
                *(float2*)&Pb[nw * 1024 + (R + 8) * 16 + cc] =
                    make_float2(accP[mi][tt][2], accP[mi][tt][3]);
            }
        __syncthreads();

        float4 o = *(float4*)&Pb[0 * 1024 + prow * 16 + jq * 4];
        float4 p1 = *(float4*)&Pb[1 * 1024 + prow * 16 + jq * 4];
        float4 p2 = *(float4*)&Pb[2 * 1024 + prow * 16 + jq * 4];
        float4 p3 = *(float4*)&Pb[3 * 1024 + prow * 16 + jq * 4];
        o.x += p1.x + p2.x + p3.x;
        o.y += p1.y + p2.y + p3.y;
        o.z += p1.z + p2.z + p3.z;
        o.w += p1.w + p2.w + p3.w;
        if (row0 + prow < Nn) Gp[(size_t)(row0 + prow) * 4 + jq] = o;
        __syncthreads();   // Pb reads done before next tile's conversion writes
    }
}

// ---------------- fused message-passing kernels ----------------
// layer-1: ONE THREAD PER EDGE. 4 independent float4 gathers (MLP=4) + 4
// fire-and-forget RED.128 + 1 degree RED. No shfl, no redundant lanes.
__global__ void scatter_l1_k(const int* __restrict__ r_src, const int* __restrict__ r_dst, int Er,
                             const int* __restrict__ di_src, const int* __restrict__ di_dst, int Edi,
                             const int* __restrict__ rb_src, const int* __restrict__ rb_dst, int Erb,
                             const int* __restrict__ db_src, const int* __restrict__ db_dst, int Edb) {
    int e = blockIdx.x * blockDim.x + threadIdx.x;
    const float4* g; float4* sum; int* deg; const int* src; const int* dst;
    if (e < Er) {
        g = (const float4*)d_gu; sum = (float4*)d_sr;  deg = d_deg_r;  src = r_src;  dst = r_dst;
    } else if ((e -= Er) < Edi) {
        g = (const float4*)d_gd; sum = (float4*)d_sdi; deg = d_deg_di; src = di_src; dst = di_dst;
    } else if ((e -= Edi) < Erb) {
        g = (const float4*)d_gm; sum = (float4*)d_au;  deg = d_deg_rb; src = rb_src; dst = rb_dst;
    } else if ((e -= Erb) < Edb) {
        g = (const float4*)d_gm; sum = (float4*)d_ad;  deg = d_deg_db; src = db_src; dst = db_dst;
    } else return;
    int s = __ldg(&src[e]);
    int d = __ldg(&dst[e]);
    float4 v0 = __ldg(&g[(size_t)s * 4 + 0]);
    float4 v1 = __ldg(&g[(size_t)s * 4 + 1]);
    float4 v2 = __ldg(&g[(size_t)s * 4 + 2]);
    float4 v3 = __ldg(&g[(size_t)s * 4 + 3]);
    atomicAdd(&deg[d], 1);
    atomicAdd(&sum[(size_t)d * 4 + 0], v0);
    atomicAdd(&sum[(size_t)d * 4 + 1], v1);
    atomicAdd(&sum[(size_t)d * 4 + 2], v2);
    atomicAdd(&sum[(size_t)d * 4 + 3], v3);
}
// g = ALPHA*g + sum/deg ; zero sums; zero deg_rb/deg_db; write movie out base
// and the precomputed 0.5/deg scales for layer-2.
__global__ void update_all_k(const float4* __restrict__ bout4, float4* __restrict__ out) {
    int i = blockIdx.x * blockDim.x + threadIdx.x;
    if (i < NU * 4) {
        int node = i >> 2;
        float4 gv = ((float4*)d_gu)[i], av = ((float4*)d_au)[i];
        int dg = d_deg_rb[node];
        float inv = 1.0f / (float)(dg > 0 ? dg : 1);
        gv.x = ALPHA * gv.x + av.x * inv; gv.y = ALPHA * gv.y + av.y * inv;
        gv.z = ALPHA * gv.z + av.z * inv; gv.w = ALPHA * gv.w + av.w * inv;
        ((float4*)d_gu)[i] = gv;
        ((float4*)d_au)[i] = make_float4(0.f, 0.f, 0.f, 0.f);
        if ((i & 3) == 0) d_deg_rb[node] = 0;
    } else if (i < (NU + NM) * 4) {
        int idx = i - NU * 4;
        int node = idx >> 2;
        float4 gv = ((float4*)d_gm)[idx];
        float4 s1 = ((float4*)d_sr)[idx], s2 = ((float4*)d_sdi)[idx];
        int dg1 = d_deg_r[node], dg2 = d_deg_di[node];
        float i1 = 0.5f / (float)(dg1 > 0 ? dg1 : 1);
        float i2 = 0.5f / (float)(dg2 > 0 ? dg2 : 1);
        gv.x = ALPHA * gv.x + s1.x * i1 + s2.x * i2;
        gv.y = ALPHA * gv.y + s1.y * i1 + s2.y * i2;
        gv.z = ALPHA * gv.z + s1.z * i1 + s2.z * i2;
        gv.w = ALPHA * gv.w + s1.w * i1 + s2.w * i2;
        ((float4*)d_gm)[idx] = gv;
        ((float4*)d_sr)[idx] = make_float4(0.f, 0.f, 0.f, 0.f);
        ((float4*)d_sdi)[idx] = make_float4(0.f, 0.f, 0.f, 0.f);
        float4 bv = __ldg(&bout4[idx & 3]);
        float4 o;
        o.x = ALPHA * gv.x + bv.x;
        o.y = ALPHA * gv.y + bv.y;
        o.z = ALPHA * gv.z + bv.z;
        o.w = ALPHA * gv.w + bv.w;
        out[idx] = o;
        if ((idx & 3) == 0) { d_invr[node] = i1; d_invdi[node] = i2; }
    } else if (i < (NU + NM + ND) * 4) {
        int idx = i - (NU + NM) * 4;
        int node = idx >> 2;
        float4 gv = ((float4*)d_gd)[idx], av = ((float4*)d_ad)[idx];
        int dg = d_deg_db[node];
        float inv = 1.0f / (float)(dg > 0 ? dg : 1);
        gv.x = ALPHA * gv.x + av.x * inv; gv.y = ALPHA * gv.y + av.y * inv;
        gv.z = ALPHA * gv.z + av.z * inv; gv.w = ALPHA * gv.w + av.w * inv;
        ((float4*)d_gd)[idx] = gv;
        ((float4*)d_ad)[idx] = make_float4(0.f, 0.f, 0.f, 0.f);
        if ((idx & 3) == 0) d_deg_db[node] = 0;
    }
}
// layer-2: ONE THREAD PER EDGE, scaled adds directly into the output
__global__ void scatter_l2_k(const int* __restrict__ r_src, const int* __restrict__ r_dst, int Er,
                             const int* __restrict__ di_src, const int* __restrict__ di_dst, int Edi,
                             float4* __restrict__ out) {
    int e = blockIdx.x * blockDim.x + threadIdx.x;
    const float4* g; const int* src; const int* dst; const float* inv;
    if (e < Er) {
        g = (const float4*)d_gu; src = r_src; dst = r_dst; inv = d_invr;
    } else if ((e -= Er) < Edi) {
        g = (const float4*)d_gd; src = di_src; dst = di_dst; inv = d_invdi;
    } else return;
    int s = __ldg(&src[e]);
    int d = __ldg(&dst[e]);
    float sc = __ldg(&inv[d]);
    float4 v0 = __ldg(&g[(size_t)s * 4 + 0]);
    float4 v1 = __ldg(&g[(size_t)s * 4 + 1]);
    float4 v2 = __ldg(&g[(size_t)s * 4 + 2]);
    float4 v3 = __ldg(&g[(size_t)s * 4 + 3]);
    v0.x *= sc; v0.y *= sc; v0.z *= sc; v0.w *= sc;
    v1.x *= sc; v1.y *= sc; v1.z *= sc; v1.w *= sc;
    v2.x *= sc; v2.y *= sc; v2.z *= sc; v2.w *= sc;
    v3.x *= sc; v3.y *= sc; v3.z *= sc; v3.w *= sc;
    atomicAdd(&out[(size_t)d * 4 + 0], v0);
    atomicAdd(&out[(size_t)d * 4 + 1], v1);
    atomicAdd(&out[(size_t)d * 4 + 2], v2);
    atomicAdd(&out[(size_t)d * 4 + 3], v3);
}
// restore deg_r/deg_di = 0 invariant
__global__ void zero_deg2_k() {
    int i = blockIdx.x * blockDim.x + threadIdx.x;
    if (i < NM) { d_deg_r[i] = 0; d_deg_di[i] = 0; }
}

// ---------------- host launch ----------------
extern "C" void kernel_launch(void* const* d_in, const int* in_sizes, int n_in,
                              void* d_out, int out_size) {
    const float *x_u, *x_m, *x_d, *W_u, *b_u, *W_m, *b_m, *W_d, *b_d, *W_o, *b_o;
    const int *r_src, *r_dst, *rb_src, *rb_dst, *di_src, *di_dst, *db_src, *db_dst;
    int Er, Erb, Edi, Edb;

    if (in_sizes[3] == 128 * 128) {
        x_u = (const float*)d_in[0];  x_m = (const float*)d_in[1];  x_d = (const float*)d_in[2];
        W_u = (const float*)d_in[3];  b_u = (const float*)d_in[4];
        W_m = (const float*)d_in[5];  b_m = (const float*)d_in[6];
        W_d = (const float*)d_in[7];  b_d = (const float*)d_in[8];
        W_o = (const float*)d_in[9];  b_o = (const float*)d_in[10];
        r_src = (const int*)d_in[11]; r_dst = (const int*)d_in[12];
        rb_src = (const int*)d_in[13]; rb_dst = (const int*)d_in[14];
        di_src = (const int*)d_in[15]; di_dst = (const int*)d_in[16];
        db_src = (const int*)d_in[17]; db_dst = (const int*)d_in[18];
        Er = in_sizes[11]; Erb = in_sizes[13]; Edi = in_sizes[15]; Edb = in_sizes[17];
    } else {
        x_u = (const float*)d_in[0];  x_m = (const float*)d_in[1];  x_d = (const float*)d_in[2];
        r_src = (const int*)d_in[3];  r_dst = (const int*)d_in[4];
        rb_src = (const int*)d_in[5]; rb_dst = (const int*)d_in[6];
        di_src = (const int*)d_in[7]; di_dst = (const int*)d_in[8];
        db_src = (const int*)d_in[9]; db_dst = (const int*)d_in[10];
        W_u = (const float*)d_in[11]; b_u = (const float*)d_in[12];
        W_m = (const float*)d_in[13]; b_m = (const float*)d_in[14];
        W_d = (const float*)d_in[15]; b_d = (const float*)d_in[16];
        W_o = (const float*)d_in[17]; b_o = (const float*)d_in[18];
        Er = in_sizes[3]; Erb = in_sizes[5]; Edi = in_sizes[7]; Edb = in_sizes[9];
    }

    float *gu, *gm, *gd;
    cudaGetSymbolAddress((void**)&gu, d_gu);
    cudaGetSymbolAddress((void**)&gm, d_gm);
    cudaGetSymbolAddress((void**)&gd, d_gd);

    cudaFuncSetAttribute(gemm_all, cudaFuncAttributeMaxDynamicSharedMemorySize, SM_TOTAL);

    const int T = 256;
    const int Etot = Er + Edi + Erb + Edb;

    // 0) one persistent GEMM for all three node types
    gemm_all<<<GEMM_GRID, 256, SM_TOTAL>>>(
        (const float4*)x_u, (const float4*)x_m, (const float4*)x_d,
        (const float4*)W_u, (const float4*)W_m, (const float4*)W_d,
        b_u, b_m, b_d, W_o,
        (float4*)gu, (float4*)gm, (float4*)gd);

    // 1) layer-1 raw-sum scatters + degree counting (1 thread/edge)
    scatter_l1_k<<<(Etot + T - 1) / T, T>>>(r_src, r_dst, Er, di_src, di_dst, Edi,
                                            rb_src, rb_dst, Erb, db_src, db_dst, Edb);
    // 2) update + movie output base + layer-2 scale precompute
    update_all_k<<<((NU + NM + ND) * 4 + T - 1) / T, T>>>((const float4*)b_o, (float4*)d_out);
    // 3) layer-2 scatters add directly into the output (1 thread/edge)
    scatter_l2_k<<<((Er + Edi) + T - 1) / T, T>>>(r_src, r_dst, Er, di_src, di_dst, Edi,
                                                  (float4*)d_out);
    // 4) restore deg_r/deg_di zero invariant
    zero_deg2_k<<<(NM + T - 1) / T, T>>>();
}

// round 12
// speedup vs baseline: 1.2171x; 1.2171x over previous
#include <cuda_runtime.h>
#include <cuda_fp16.h>
#include <cstdint>

#define NU 200000
#define NM 100000
#define ND 20000
#define ALPHA 0.01f

#define T0_TILES 3125              // ceil(NU/64)
#define T1_TILES 1563              // ceil(NM/64)
#define T2_TILES 313               // ceil(ND/64)
#define TB1 T0_TILES
#define TB2 (T0_TILES + T1_TILES)
#define TT  (T0_TILES + T1_TILES + T2_TILES)   // 5001

// ---------------- persistent device scratch (zero-initialized at load) ----------------
__device__ float d_gu[NU * 16];
__device__ float d_gm[NM * 16];
__device__ float d_gd[ND * 16];
__device__ float d_au[NU * 16];   // raw-sum buffers: zero at entry/exit invariant
__device__ float d_ad[ND * 16];
__device__ float d_sr[NM * 16];   // movie sums from 'rates'
__device__ float d_sdi[NM * 16];  // movie sums from 'dir'
__device__ int   d_deg_r[NM];     // degree counters: zero at entry/exit invariant
__device__ int   d_deg_di[NM];
__device__ int   d_deg_rb[NU];
__device__ int   d_deg_db[ND];
__device__ float d_invr[NM];      // 0.5/deg scales for layer-2 (written by update_all)
__device__ float d_invdi[NM];

// ---------------- helpers ----------------
__device__ __forceinline__ uint32_t smem_u32(const void* p) {
    uint32_t a;
    asm("{ .reg .u64 t; cvta.to.shared.u64 t, %1; cvt.u32.u64 %0, t; }" : "=r"(a) : "l"(p));
    return a;
}
__device__ __forceinline__ void ldmx4(uint32_t& a0, uint32_t& a1, uint32_t& a2, uint32_t& a3,
                                      uint32_t addr) {
    asm volatile("ldmatrix.sync.aligned.m8n8.x4.shared.b16 {%0,%1,%2,%3}, [%4];"
                 : "=r"(a0), "=r"(a1), "=r"(a2), "=r"(a3) : "r"(addr));
}
__device__ __forceinline__ void mma_h(float& c0, float& c1, float& c2, float& c3,
                                      uint32_t a0, uint32_t a1, uint32_t a2, uint32_t a3,
                                      uint32_t b0, uint32_t b1) {
    asm volatile("mma.sync.aligned.m16n8k16.row.col.f32.f16.f16.f32 "
                 "{%0,%1,%2,%3}, {%4,%5,%6,%7}, {%8,%9}, {%0,%1,%2,%3};"
                 : "+f"(c0), "+f"(c1), "+f"(c2), "+f"(c3)
                 : "r"(a0), "r"(a1), "r"(a2), "r"(a3), "r"(b0), "r"(b1));
}
__device__ __forceinline__ uint32_t pack_h2(float x, float y) {
    __half2 h = __floats2half2_rn(x, y);
    return *(uint32_t*)&h;
}
__device__ __forceinline__ void cp16(uint32_t dst, const void* src, int pbytes) {
    asm volatile("cp.async.cg.shared.global [%0], [%1], 16, %2;"
                 :: "r"(dst), "l"(src), "r"(pbytes));
}
#define CP_COMMIT() asm volatile("cp.async.commit_group;" ::: "memory")
#define CP_WAIT0()  asm volatile("cp.async.wait_group 0;" ::: "memory")

// ---------------- persistent fused GEMM over all 3 node types ----------------
// G = relu(X @ W^T + b) @ Wout^T. fp16 hi-only A/B/H/Wout (calibrated ~2.2e-4).
// cp.async double-buffers raw X.
// smem: A[64][136]h @0 (17408) | B[128][136]h @17408 (34816) | RAW f32 @52224 (32768)
//       Pb[4][64][16]f32 (16KB) aliases A after the MMA mainloop.
#define PDA 136
#define OFF_A   0
#define OFF_B   17408
#define OFF_RAW 52224
#define SM_TOTAL 84992
#define GEMM_GRID 296

__global__ void __launch_bounds__(256, 2)
gemm_all(const float4* __restrict__ Xu, const float4* __restrict__ Xm,
         const float4* __restrict__ Xd,
         const float4* __restrict__ Wu, const float4* __restrict__ Wm,
         const float4* __restrict__ Wd,
         const float* __restrict__ bu, const float* __restrict__ bm,
         const float* __restrict__ bd,
         const float* __restrict__ Wout,
         float4* __restrict__ Gu, float4* __restrict__ Gm, float4* __restrict__ Gd) {
    extern __shared__ __align__(16) char smem[];
    const uint32_t sb = smem_u32(smem);
    const int tid = threadIdx.x;
    const int wid = tid >> 5;
    const int lane = tid & 31;

    const int t0 = (int)(((long long)blockIdx.x * TT) / GEMM_GRID);
    const int t1 = (int)(((long long)(blockIdx.x + 1) * TT) / GEMM_GRID);

    const int mw = wid >> 2;
    const int nw = wid & 3;
    const int a_r = (lane & 15);
    const int a_k8 = (lane >> 4) * 8;
    const int b_r = (lane & 7) + ((lane >> 4) << 3);
    const int b_k8 = ((lane >> 3) & 1) * 8;
    const int crow = lane >> 2;
    const int ccol2 = (lane & 3) * 2;
    const int prow = tid >> 2;
    const int jq = tid & 3;

    // ---- Wout B-fragments (fp16 hi) — ONCE ----
    uint32_t wo[2][2][2];
    {
        const int wn = lane >> 2;
#pragma unroll
        for (int kl = 0; kl < 2; kl++)
#pragma unroll
            for (int t = 0; t < 2; t++) {
                const float* wr = Wout + (size_t)(t * 8 + wn) * 128 + nw * 32 + kl * 16;
                wo[kl][t][0] = pack_h2(wr[ccol2], wr[ccol2 + 1]);
                wo[kl][t][1] = pack_h2(wr[8 + ccol2], wr[9 + ccol2]);
            }
    }

    float* Pb = (float*)(smem + OFF_A);
    float2 biasr[4];
    int curtype = -1;

    // ---- preamble: prefetch raw X for first tile ----
    {
        int t = t0;
        int ty = (t >= TB2) ? 2 : (t >= TB1) ? 1 : 0;
        int lt = t - (ty == 2 ? TB2 : ty == 1 ? TB1 : 0);
        const float4* Xp = (ty == 0) ? Xu : (ty == 1) ? Xm : Xd;
        int Nn = (ty == 0) ? NU : (ty == 1) ? NM : ND;
        int row0 = lt * 64;
#pragma unroll
        for (int u = 0; u < 8; u++) {
            int idx = tid + u * 256;
            int row = row0 + (idx >> 5);
            int ok = row < Nn;
            const float4* src = Xp + (size_t)(ok ? row : 0) * 32 + (idx & 31);
            cp16(sb + OFF_RAW + idx * 16, src, ok ? 16 : 0);
        }
        CP_COMMIT();
    }

    for (int t = t0; t < t1; t++) {
        const int ty = (t >= TB2) ? 2 : (t >= TB1) ? 1 : 0;
        const int lt = t - (ty == 2 ? TB2 : ty == 1 ? TB1 : 0);
        const int Nn = (ty == 0) ? NU : (ty == 1) ? NM : ND;
        float4* Gp = (ty == 0) ? Gu : (ty == 1) ? Gm : Gd;
        const int row0 = lt * 64;

        if (ty != curtype) {
            const float4* Wp = (ty == 0) ? Wu : (ty == 1) ? Wm : Wd;
            const float* bp = (ty == 0) ? bu : (ty == 1) ? bm : bd;
#pragma unroll
            for (int u = 0; u < 16; u++) {
                int idx = tid + u * 256;
                int row = idx >> 5, q4 = idx & 31;
                float4 v = Wp[(size_t)row * 32 + q4];
                uint32_t h0 = pack_h2(v.x, v.y);
                uint32_t h1 = pack_h2(v.z, v.w);
                *(uint2*)(smem + OFF_B + (row * PDA + q4 * 4) * 2) = make_uint2(h0, h1);
            }
#pragma unroll
            for (int ni = 0; ni < 4; ni++)
                biasr[ni] = *(const float2*)&bp[nw * 32 + ni * 8 + ccol2];
            curtype = ty;
        }

        CP_WAIT0();
        __syncthreads();                 // raw(t) + B visible

        // ---- convert raw fp32 -> A fp16 (hi only) ----
#pragma unroll
        for (int u = 0; u < 8; u++) {
            int idx = tid + u * 256;
            int row = idx >> 5, q4 = idx & 31;
            float4 v = ((const float4*)(smem + OFF_RAW))[idx];
            uint32_t h0 = pack_h2(v.x, v.y);
            uint32_t h1 = pack_h2(v.z, v.w);
            *(uint2*)(smem + OFF_A + (row * PDA + q4 * 4) * 2) = make_uint2(h0, h1);
        }
        __syncthreads();                 // A ready; raw buffer free

        // ---- prefetch next tile's raw X (overlaps MMA) ----
        if (t + 1 < t1) {
            int tn = t + 1;
            int tyn = (tn >= TB2) ? 2 : (tn >= TB1) ? 1 : 0;
            int ltn = tn - (tyn == 2 ? TB2 : tyn == 1 ? TB1 : 0);
            const float4* Xn = (tyn == 0) ? Xu : (tyn == 1) ? Xm : Xd;
            int Nx = (tyn == 0) ? NU : (tyn == 1) ? NM : ND;
            int r0n = ltn * 64;
#pragma unroll
            for (int u = 0; u < 8; u++) {
                int idx = tid + u * 256;
                int row = r0n + (idx >> 5);
                int ok = row < Nx;
                const float4* src = Xn + (size_t)(ok ? row : 0) * 32 + (idx & 31);
                cp16(sb + OFF_RAW + idx * 16, src, ok ? 16 : 0);
            }
            CP_COMMIT();
        }

        // ---- MMA mainloop: acc = A @ B^T ----
        float acc[2][4][4];
#pragma unroll
        for (int mi = 0; mi < 2; mi++)
#pragma unroll
            for (int ni = 0; ni < 4; ni++)
#pragma unroll
                for (int e = 0; e < 4; e++) acc[mi][ni][e] = 0.0f;

#pragma unroll 2
        for (int k16 = 0; k16 < 8; k16++) {
            const int k0 = k16 * 16;
            uint32_t ah[2][4], bb[2][4];
#pragma unroll
            for (int mi = 0; mi < 2; mi++) {
                int row = mw * 32 + mi * 16 + a_r;
                uint32_t off = (uint32_t)(row * PDA + k0 + a_k8) * 2;
                ldmx4(ah[mi][0], ah[mi][1], ah[mi][2], ah[mi][3], sb + OFF_A + off);
            }
#pragma unroll
            for (int np = 0; np < 2; np++) {
                int row = nw * 32 + np * 16 + b_r;
                uint32_t off = (uint32_t)(row * PDA + k0 + b_k8) * 2;
                ldmx4(bb[np][0], bb[np][1], bb[np][2], bb[np][3], sb + OFF_B + off);
            }
#pragma unroll
            for (int mi = 0; mi < 2; mi++)
#pragma unroll
                for (int ni = 0; ni < 4; ni++) {
                    int np = ni >> 1, half = (ni & 1) * 2;
                    float* c = acc[mi][ni];
                    mma_h(c[0], c[1], c[2], c[3],
                          ah[mi][0], ah[mi][1], ah[mi][2], ah[mi][3],
                          bb[np][half], bb[np][half + 1]);
                }
        }
        __syncthreads();   // A reads done before Pb aliases it

        // ---- bias + relu in regs; tensor-core projection (H hi, Wout hi) ----
        float accP[2][2][4];
#pragma unroll
        for (int mi = 0; mi < 2; mi++)
#pragma unroll
            for (int tt = 0; tt < 2; tt++)
#pragma unroll
                for (int e = 0; e < 4; e++) accP[mi][tt][e] = 0.0f;

#pragma unroll
        for (int mi = 0; mi < 2; mi++) {
#pragma unroll
            for (int ni = 0; ni < 4; ni++) {
                float* c = acc[mi][ni];
                c[0] = fmaxf(c[0] + biasr[ni].x, 0.0f);
                c[1] = fmaxf(c[1] + biasr[ni].y, 0.0f);
                c[2] = fmaxf(c[2] + biasr[ni].x, 0.0f);
                c[3] = fmaxf(c[3] + biasr[ni].y, 0.0f);
            }
#pragma unroll
            for (int kl = 0; kl < 2; kl++) {
                float* L = acc[mi][2 * kl];
                float* R = acc[mi][2 * kl + 1];
                uint32_t a0 = pack_h2(L[0], L[1]);
                uint32_t a1 = pack_h2(L[2], L[3]);
                uint32_t a2 = pack_h2(R[0], R[1]);
                uint32_t a3 = pack_h2(R[2], R[3]);
#pragma unroll
                for (int tt = 0; tt < 2; tt++) {
                    float* p = accP[mi][tt];
                    mma_h(p[0], p[1], p[2], p[3], a0, a1, a2, a3,
                          wo[kl][tt][0], wo[kl][tt][1]);
                }
            }
        }

        // ---- write per-warp partials, k-reduce across the 4 nw warps ----
#pragma unroll
        for (int mi = 0; mi < 2; mi++)
#pragma unroll
            for (int tt = 0; tt < 2; tt++) {
                int R = mw * 32 + mi * 16 + crow;
                int cc = tt * 8 + ccol2;
                *(float2*)&Pb[nw * 1024 + R * 16 + cc] =
                    make_float2(accP[mi][tt][0], accP[mi][tt][1]);
                *(float2*)&Pb[nw * 1024 + (R + 8) * 16 + cc] =
                    make_float2(accP[mi][tt][2], accP[mi][tt][3]);
            }
        __syncthreads();

        float4 o = *(float4*)&Pb[0 * 1024 + prow * 16 + jq * 4];
        float4 p1 = *(float4*)&Pb[1 * 1024 + prow * 16 + jq * 4];
        float4 p2 = *(float4*)&Pb[2 * 1024 + prow * 16 + jq * 4];
        float4 p3 = *(float4*)&Pb[3 * 1024 + prow * 16 + jq * 4];
        o.x += p1.x + p2.x + p3.x;
        o.y += p1.y + p2.y + p3.y;
        o.z += p1.z + p2.z + p3.z;
        o.w += p1.w + p2.w + p3.w;
        if (row0 + prow < Nn) Gp[(size_t)(row0 + prow) * 4 + jq] = o;
        __syncthreads();   // Pb reads done before next tile's conversion writes
    }
}

// ---------------- fused message-passing kernels ----------------
// layer-1: 4 threads/edge (lane-contiguous 64B gather/scatter), direct index
// loads (coalescer merges the same-address loads across the 4 lanes).
__global__ void scatter_l1_k(const int* __restrict__ r_src, const int* __restrict__ r_dst, int Er,
                             const int* __restrict__ di_src, const int* __restrict__ di_dst, int Edi,
                             const int* __restrict__ rb_src, const int* __restrict__ rb_dst, int Erb,
                             const int* __restrict__ db_src, const int* __restrict__ db_dst, int Edb) {
    int t = blockIdx.x * blockDim.x + threadIdx.x;
    int e = t >> 2, q = t & 3;
    const float4* g; float4* sum; int* deg; const int* src; const int* dst;
    if (e < Er) {
        g = (const float4*)d_gu; sum = (float4*)d_sr;  deg = d_deg_r;  src = r_src;  dst = r_dst;
    } else if ((e -= Er) < Edi) {
        g = (const float4*)d_gd; sum = (float4*)d_sdi; deg = d_deg_di; src = di_src; dst = di_dst;
    } else if ((e -= Edi) < Erb) {
        g = (const float4*)d_gm; sum = (float4*)d_au;  deg = d_deg_rb; src = rb_src; dst = rb_dst;
    } else if ((e -= Erb) < Edb) {
        g = (const float4*)d_gm; sum = (float4*)d_ad;  deg = d_deg_db; src = db_src; dst = db_dst;
    } else return;
    int s = __ldg(&src[e]);
    int d = __ldg(&dst[e]);
    float4 v = __ldg(&g[(size_t)s * 4 + q]);
    atomicAdd(&sum[(size_t)d * 4 + q], v);
    if (q == 0) atomicAdd(&deg[d], 1);
}
// g = ALPHA*g + sum/deg ; zero sums + ALL degree counters; write movie out
// base and the precomputed 0.5/deg scales for layer-2.
__global__ void update_all_k(const float4* __restrict__ bout4, float4* __restrict__ out) {
    int i = blockIdx.x * blockDim.x + threadIdx.x;
    if (i < NU * 4) {
        int node = i >> 2;
        float4 gv = ((float4*)d_gu)[i], av = ((float4*)d_au)[i];
        int dg = d_deg_rb[node];
        float inv = 1.0f / (float)(dg > 0 ? dg : 1);
        gv.x = ALPHA * gv.x + av.x * inv; gv.y = ALPHA * gv.y + av.y * inv;
        gv.z = ALPHA * gv.z + av.z * inv; gv.w = ALPHA * gv.w + av.w * inv;
        ((float4*)d_gu)[i] = gv;
        ((float4*)d_au)[i] = make_float4(0.f, 0.f, 0.f, 0.f);
        if ((i & 3) == 0) d_deg_rb[node] = 0;
    } else if (i < (NU + NM) * 4) {
        int idx = i - NU * 4;
        int node = idx >> 2;
        float4 gv = ((float4*)d_gm)[idx];
        float4 s1 = ((float4*)d_sr)[idx], s2 = ((float4*)d_sdi)[idx];
        int dg1 = d_deg_r[node], dg2 = d_deg_di[node];
        float i1 = 0.5f / (float)(dg1 > 0 ? dg1 : 1);
        float i2 = 0.5f / (float)(dg2 > 0 ? dg2 : 1);
        gv.x = ALPHA * gv.x + s1.x * i1 + s2.x * i2;
        gv.y = ALPHA * gv.y + s1.y * i1 + s2.y * i2;
        gv.z = ALPHA * gv.z + s1.z * i1 + s2.z * i2;
        gv.w = ALPHA * gv.w + s1.w * i1 + s2.w * i2;
        ((float4*)d_gm)[idx] = gv;
        ((float4*)d_sr)[idx] = make_float4(0.f, 0.f, 0.f, 0.f);
        ((float4*)d_sdi)[idx] = make_float4(0.f, 0.f, 0.f, 0.f);
        float4 bv = __ldg(&bout4[idx & 3]);
        float4 o;
        o.x = ALPHA * gv.x + bv.x;
        o.y = ALPHA * gv.y + bv.y;
        o.z = ALPHA * gv.z + bv.z;
        o.w = ALPHA * gv.w + bv.w;
        out[idx] = o;
        // layer-2 reads only d_invr/d_invdi, so the counters can be zeroed now
        if ((idx & 3) == 0) {
            d_invr[node] = i1; d_invdi[node] = i2;
            d_deg_r[node] = 0; d_deg_di[node] = 0;
        }
    } else if (i < (NU + NM + ND) * 4) {
        int idx = i - (NU + NM) * 4;
        int node = idx >> 2;
        float4 gv = ((float4*)d_gd)[idx], av = ((float4*)d_ad)[idx];
        int dg = d_deg_db[node];
        float inv = 1.0f / (float)(dg > 0 ? dg : 1);
        gv.x = ALPHA * gv.x + av.x * inv; gv.y = ALPHA * gv.y + av.y * inv;
        gv.z = ALPHA * gv.z + av.z * inv; gv.w = ALPHA * gv.w + av.w * inv;
        ((float4*)d_gd)[idx] = gv;
        ((float4*)d_ad)[idx] = make_float4(0.f, 0.f, 0.f, 0.f);
        if ((idx & 3) == 0) d_deg_db[node] = 0;
    }
}
// layer-2: 4 threads/edge, scaled adds directly into the output
__global__ void scatter_l2_k(const int* __restrict__ r_src, const int* __restrict__ r_dst, int Er,
                             const int* __restrict__ di_src, const int* __restrict__ di_dst, int Edi,
                             float4* __restrict__ out) {
    int t = blockIdx.x * blockDim.x + threadIdx.x;
    int e = t >> 2, q = t & 3;
    const float4* g; const int* src; const int* dst; const float* inv;
    if (e < Er) {
        g = (const float4*)d_gu; src = r_src; dst = r_dst; inv = d_invr;
    } else if ((e -= Er) < Edi) {
        g = (const float4*)d_gd; src = di_src; dst = di_dst; inv = d_invdi;
    } else return;
    int s = __ldg(&src[e]);
    int d = __ldg(&dst[e]);
    float sc = __ldg(&inv[d]);
    float4 v = __ldg(&g[(size_t)s * 4 + q]);
    v.x *= sc; v.y *= sc; v.z *= sc; v.w *= sc;
    atomicAdd(&out[(size_t)d * 4 + q], v);
}

// ---------------- host launch ----------------
extern "C" void kernel_launch(void* const* d_in, const int* in_sizes, int n_in,
                              void* d_out, int out_size) {
    const float *x_u, *x_m, *x_d, *W_u, *b_u, *W_m, *b_m, *W_d, *b_d, *W_o, *b_o;
    const int *r_src, *r_dst, *rb_src, *rb_dst, *di_src, *di_dst, *db_src, *db_dst;
    int Er, Erb, Edi, Edb;

    if (in_sizes[3] == 128 * 128) {
        x_u = (const float*)d_in[0];  x_m = (const float*)d_in[1];  x_d = (const float*)d_in[2];
        W_u = (const float*)d_in[3];  b_u = (const float*)d_in[4];
        W_m = (const float*)d_in[5];  b_m = (const float*)d_in[6];
        W_d = (const float*)d_in[7];  b_d = (const float*)d_in[8];
        W_o = (const float*)d_in[9];  b_o = (const float*)d_in[10];
        r_src = (const int*)d_in[11]; r_dst = (const int*)d_in[12];
        rb_src = (const int*)d_in[13]; rb_dst = (const int*)d_in[14];
        di_src = (const int*)d_in[15]; di_dst = (const int*)d_in[16];
        db_src = (const int*)d_in[17]; db_dst = (const int*)d_in[18];
        Er = in_sizes[11]; Erb = in_sizes[13]; Edi = in_sizes[15]; Edb = in_sizes[17];
    } else {
        x_u = (const float*)d_in[0];  x_m = (const float*)d_in[1];  x_d = (const float*)d_in[2];
        r_src = (const int*)d_in[3];  r_dst = (const int*)d_in[4];
        rb_src = (const int*)d_in[5]; rb_dst = (const int*)d_in[6];
        di_src = (const int*)d_in[7]; di_dst = (const int*)d_in[8];
        db_src = (const int*)d_in[9]; db_dst = (const int*)d_in[10];
        W_u = (const float*)d_in[11]; b_u = (const float*)d_in[12];
        W_m = (const float*)d_in[13]; b_m = (const float*)d_in[14];
        W_d = (const float*)d_in[15]; b_d = (const float*)d_in[16];
        W_o = (const float*)d_in[17]; b_o = (const float*)d_in[18];
        Er = in_sizes[3]; Erb = in_sizes[5]; Edi = in_sizes[7]; Edb = in_sizes[9];
    }

    float *gu, *gm, *gd;
    cudaGetSymbolAddress((void**)&gu, d_gu);
    cudaGetSymbolAddress((void**)&gm, d_gm);
    cudaGetSymbolAddress((void**)&gd, d_gd);

    cudaFuncSetAttribute(gemm_all, cudaFuncAttributeMaxDynamicSharedMemorySize, SM_TOTAL);

    const int T = 256;
    const int Etot = Er + Edi + Erb + Edb;

    // 0) one persistent GEMM for all three node types
    gemm_all<<<GEMM_GRID, 256, SM_TOTAL>>>(
        (const float4*)x_u, (const float4*)x_m, (const float4*)x_d,
        (const float4*)W_u, (const float4*)W_m, (const float4*)W_d,
        b_u, b_m, b_d, W_o,
        (float4*)gu, (float4*)gm, (float4*)gd);

    // 1) layer-1 raw-sum scatters + degree counting (4 threads/edge)
    scatter_l1_k<<<(Etot * 4 + T - 1) / T, T>>>(r_src, r_dst, Er, di_src, di_dst, Edi,
                                                rb_src, rb_dst, Erb, db_src, db_dst, Edb);
    // 2) update + movie output base + layer-2 scales + counter re-zero
    update_all_k<<<((NU + NM + ND) * 4 + T - 1) / T, T>>>((const float4*)b_o, (float4*)d_out);
    // 3) layer-2 scatters add directly into the output (4 threads/edge)
    scatter_l2_k<<<((Er + Edi) * 4 + T - 1) / T, T>>>(r_src, r_dst, Er, di_src, di_dst, Edi,
                                                      (float4*)d_out);
}

// round 13
// speedup vs baseline: 1.2523x; 1.0289x over previous
#include <cuda_runtime.h>
#include <cuda_fp16.h>
#include <cstdint>

#define NU 200000
#define NM 100000
#define ND 20000
#define ALPHA 0.01f

#define T0_TILES 3125              // ceil(NU/64)
#define T1_TILES 1563              // ceil(NM/64)
#define T2_TILES 313               // ceil(ND/64)
#define TB1 T0_TILES
#define TB2 (T0_TILES + T1_TILES)
#define TT  (T0_TILES + T1_TILES + T2_TILES)   // 5001

// ---------------- persistent device scratch (zero-initialized at load) ----------------
// G features stored as fp16 (half2-packed): 8 uint32 per node row (16 halves).
__device__ uint32_t d_gu[NU * 8];
__device__ uint32_t d_gm[NM * 8];
__device__ uint32_t d_gd[ND * 8];
__device__ float d_au[NU * 16];   // raw-sum buffers (fp32): zero at entry/exit invariant
__device__ float d_ad[ND * 16];
__device__ float d_sr[NM * 16];   // movie sums from 'rates'
__device__ float d_sdi[NM * 16];  // movie sums from 'dir'
__device__ int   d_deg_r[NM];     // degree counters: zero at entry/exit invariant
__device__ int   d_deg_di[NM];
__device__ int   d_deg_rb[NU];
__device__ int   d_deg_db[ND];
__device__ float d_invr[NM];      // 0.5/deg scales for layer-2 (written by update_all)
__device__ float d_invdi[NM];

// ---------------- helpers ----------------
__device__ __forceinline__ uint32_t smem_u32(const void* p) {
    uint32_t a;
    asm("{ .reg .u64 t; cvta.to.shared.u64 t, %1; cvt.u32.u64 %0, t; }" : "=r"(a) : "l"(p));
    return a;
}
__device__ __forceinline__ void ldmx4(uint32_t& a0, uint32_t& a1, uint32_t& a2, uint32_t& a3,
                                      uint32_t addr) {
    asm volatile("ldmatrix.sync.aligned.m8n8.x4.shared.b16 {%0,%1,%2,%3}, [%4];"
                 : "=r"(a0), "=r"(a1), "=r"(a2), "=r"(a3) : "r"(addr));
}
__device__ __forceinline__ void mma_h(float& c0, float& c1, float& c2, float& c3,
                                      uint32_t a0, uint32_t a1, uint32_t a2, uint32_t a3,
                                      uint32_t b0, uint32_t b1) {
    asm volatile("mma.sync.aligned.m16n8k16.row.col.f32.f16.f16.f32 "
                 "{%0,%1,%2,%3}, {%4,%5,%6,%7}, {%8,%9}, {%0,%1,%2,%3};"
                 : "+f"(c0), "+f"(c1), "+f"(c2), "+f"(c3)
                 : "r"(a0), "r"(a1), "r"(a2), "r"(a3), "r"(b0), "r"(b1));
}
__device__ __forceinline__ uint32_t pack_h2(float x, float y) {
    __half2 h = __floats2half2_rn(x, y);
    return *(uint32_t*)&h;
}
__device__ __forceinline__ float2 unpack_h2(uint32_t u) {
    return __half22float2(*(__half2*)&u);
}
__device__ __forceinline__ void cp16(uint32_t dst, const void* src, int pbytes) {
    asm volatile("cp.async.cg.shared.global [%0], [%1], 16, %2;"
                 :: "r"(dst), "l"(src), "r"(pbytes));
}
#define CP_COMMIT() asm volatile("cp.async.commit_group;" ::: "memory")
#define CP_WAIT0()  asm volatile("cp.async.wait_group 0;" ::: "memory")

// ---------------- persistent fused GEMM over all 3 node types ----------------
// G(fp16) = relu(X @ W^T + b) @ Wout^T. fp16 hi-only A/B/H/Wout.
// cp.async double-buffers raw X.
// smem: A[64][136]h @0 (17408) | B[128][136]h @17408 (34816) | RAW f32 @52224 (32768)
//       Pb[4][64][16]f32 (16KB) aliases A after the MMA mainloop.
#define PDA 136
#define OFF_A   0
#define OFF_B   17408
#define OFF_RAW 52224
#define SM_TOTAL 84992
#define GEMM_GRID 296

__global__ void __launch_bounds__(256, 2)
gemm_all(const float4* __restrict__ Xu, const float4* __restrict__ Xm,
         const float4* __restrict__ Xd,
         const float4* __restrict__ Wu, const float4* __restrict__ Wm,
         const float4* __restrict__ Wd,
         const float* __restrict__ bu, const float* __restrict__ bm,
         const float* __restrict__ bd,
         const float* __restrict__ Wout,
         uint32_t* __restrict__ Gu, uint32_t* __restrict__ Gm, uint32_t* __restrict__ Gd) {
    extern __shared__ __align__(16) char smem[];
    const uint32_t sb = smem_u32(smem);
    const int tid = threadIdx.x;
    const int wid = tid >> 5;
    const int lane = tid & 31;

    const int t0 = (int)(((long long)blockIdx.x * TT) / GEMM_GRID);
    const int t1 = (int)(((long long)(blockIdx.x + 1) * TT) / GEMM_GRID);

    const int mw = wid >> 2;
    const int nw = wid & 3;
    const int a_r = (lane & 15);
    const int a_k8 = (lane >> 4) * 8;
    const int b_r = (lane & 7) + ((lane >> 4) << 3);
    const int b_k8 = ((lane >> 3) & 1) * 8;
    const int crow = lane >> 2;
    const int ccol2 = (lane & 3) * 2;
    const int prow = tid >> 2;
    const int jq = tid & 3;

    // ---- Wout B-fragments (fp16 hi) — ONCE ----
    uint32_t wo[2][2][2];
    {
        const int wn = lane >> 2;
#pragma unroll
        for (int kl = 0; kl < 2; kl++)
#pragma unroll
            for (int t = 0; t < 2; t++) {
                const float* wr = Wout + (size_t)(t * 8 + wn) * 128 + nw * 32 + kl * 16;
                wo[kl][t][0] = pack_h2(wr[ccol2], wr[ccol2 + 1]);
                wo[kl][t][1] = pack_h2(wr[8 + ccol2], wr[9 + ccol2]);
            }
    }

    float* Pb = (float*)(smem + OFF_A);
    float2 biasr[4];
    int curtype = -1;

    // ---- preamble: prefetch raw X for first tile ----
    {
        int t = t0;
        int ty = (t >= TB2) ? 2 : (t >= TB1) ? 1 : 0;
        int lt = t - (ty == 2 ? TB2 : ty == 1 ? TB1 : 0);
        const float4* Xp = (ty == 0) ? Xu : (ty == 1) ? Xm : Xd;
        int Nn = (ty == 0) ? NU : (ty == 1) ? NM : ND;
        int row0 = lt * 64;
#pragma unroll
        for (int u = 0; u < 8; u++) {
            int idx = tid + u * 256;
            int row = row0 + (idx >> 5);
            int ok = row < Nn;
            const float4* src = Xp + (size_t)(ok ? row : 0) * 32 + (idx & 31);
            cp16(sb + OFF_RAW + idx * 16, src, ok ? 16 : 0);
        }
        CP_COMMIT();
    }

    for (int t = t0; t < t1; t++) {
        const int ty = (t >= TB2) ? 2 : (t >= TB1) ? 1 : 0;
        const int lt = t - (ty == 2 ? TB2 : ty == 1 ? TB1 : 0);
        const int Nn = (ty == 0) ? NU : (ty == 1) ? NM : ND;
        uint32_t* Gp = (ty == 0) ? Gu : (ty == 1) ? Gm : Gd;
        const int row0 = lt * 64;

        if (ty != curtype) {
            const float4* Wp = (ty == 0) ? Wu : (ty == 1) ? Wm : Wd;
            const float* bp = (ty == 0) ? bu : (ty == 1) ? bm : bd;
#pragma unroll
            for (int u = 0; u < 16; u++) {
                int idx = tid + u * 256;
                int row = idx >> 5, q4 = idx & 31;
                float4 v = Wp[(size_t)row * 32 + q4];
                uint32_t h0 = pack_h2(v.x, v.y);
                uint32_t h1 = pack_h2(v.z, v.w);
                *(uint2*)(smem + OFF_B + (row * PDA + q4 * 4) * 2) = make_uint2(h0, h1);
            }
#pragma unroll
            for (int ni = 0; ni < 4; ni++)
                biasr[ni] = *(const float2*)&bp[nw * 32 + ni * 8 + ccol2];
            curtype = ty;
        }

        CP_WAIT0();
        __syncthreads();                 // raw(t) + B visible

        // ---- convert raw fp32 -> A fp16 (hi only) ----
#pragma unroll
        for (int u = 0; u < 8; u++) {
            int idx = tid + u * 256;
            int row = idx >> 5, q4 = idx & 31;
            float4 v = ((const float4*)(smem + OFF_RAW))[idx];
            uint32_t h0 = pack_h2(v.x, v.y);
            uint32_t h1 = pack_h2(v.z, v.w);
            *(uint2*)(smem + OFF_A + (row * PDA + q4 * 4) * 2) = make_uint2(h0, h1);
        }
        __syncthreads();                 // A ready; raw buffer free

        // ---- prefetch next tile's raw X (overlaps MMA) ----
        if (t + 1 < t1) {
            int tn = t + 1;
            int tyn = (tn >= TB2) ? 2 : (tn >= TB1) ? 1 : 0;
            int ltn = tn - (tyn == 2 ? TB2 : tyn == 1 ? TB1 : 0);
            const float4* Xn = (tyn == 0) ? Xu : (tyn == 1) ? Xm : Xd;
            int Nx = (tyn == 0) ? NU : (tyn == 1) ? NM : ND;
            int r0n = ltn * 64;
#pragma unroll
            for (int u = 0; u < 8; u++) {
                int idx = tid + u * 256;
                int row = r0n + (idx >> 5);
                int ok = row < Nx;
                const float4* src = Xn + (size_t)(ok ? row : 0) * 32 + (idx & 31);
                cp16(sb + OFF_RAW + idx * 16, src, ok ? 16 : 0);
            }
            CP_COMMIT();
        }

        // ---- MMA mainloop: acc = A @ B^T ----
        float acc[2][4][4];
#pragma unroll
        for (int mi = 0; mi < 2; mi++)
#pragma unroll
            for (int ni = 0; ni < 4; ni++)
#pragma unroll
                for (int e = 0; e < 4; e++) acc[mi][ni][e] = 0.0f;

#pragma unroll 2
        for (int k16 = 0; k16 < 8; k16++) {
            const int k0 = k16 * 16;
            uint32_t ah[2][4], bb[2][4];
#pragma unroll
            for (int mi = 0; mi < 2; mi++) {
                int row = mw * 32 + mi * 16 + a_r;
                uint32_t off = (uint32_t)(row * PDA + k0 + a_k8) * 2;
                ldmx4(ah[mi][0], ah[mi][1], ah[mi][2], ah[mi][3], sb + OFF_A + off);
            }
#pragma unroll
            for (int np = 0; np < 2; np++) {
                int row = nw * 32 + np * 16 + b_r;
                uint32_t off = (uint32_t)(row * PDA + k0 + b_k8) * 2;
                ldmx4(bb[np][0], bb[np][1], bb[np][2], bb[np][3], sb + OFF_B + off);
            }
#pragma unroll
            for (int mi = 0; mi < 2; mi++)
#pragma unroll
                for (int ni = 0; ni < 4; ni++) {
                    int np = ni >> 1, half = (ni & 1) * 2;
                    float* c = acc[mi][ni];
                    mma_h(c[0], c[1], c[2], c[3],
                          ah[mi][0], ah[mi][1], ah[mi][2], ah[mi][3],
                          bb[np][half], bb[np][half + 1]);
                }
        }
        __syncthreads();   // A reads done before Pb aliases it

        // ---- bias + relu in regs; tensor-core projection (H hi, Wout hi) ----
        float accP[2][2][4];
#pragma unroll
        for (int mi = 0; mi < 2; mi++)
#pragma unroll
            for (int tt = 0; tt < 2; tt++)
#pragma unroll
                for (int e = 0; e < 4; e++) accP[mi][tt][e] = 0.0f;

#pragma unroll
        for (int mi = 0; mi < 2; mi++) {
#pragma unroll
            for (int ni = 0; ni < 4; ni++) {
                float* c = acc[mi][ni];
                c[0] = fmaxf(c[0] + biasr[ni].x, 0.0f);
                c[1] = fmaxf(c[1] + biasr[ni].y, 0.0f);
                c[2] = fmaxf(c[2] + biasr[ni].x, 0.0f);
                c[3] = fmaxf(c[3] + biasr[ni].y, 0.0f);
            }
#pragma unroll
            for (int kl = 0; kl < 2; kl++) {
                float* L = acc[mi][2 * kl];
                float* R = acc[mi][2 * kl + 1];
                uint32_t a0 = pack_h2(L[0], L[1]);
                uint32_t a1 = pack_h2(L[2], L[3]);
                uint32_t a2 = pack_h2(R[0], R[1]);
                uint32_t a3 = pack_h2(R[2], R[3]);
#pragma unroll
                for (int tt = 0; tt < 2; tt++) {
                    float* p = accP[mi][tt];
                    mma_h(p[0], p[1], p[2], p[3], a0, a1, a2, a3,
                          wo[kl][tt][0], wo[kl][tt][1]);
                }
            }
        }

        // ---- write per-warp partials, k-reduce across the 4 nw warps ----
#pragma unroll
        for (int mi = 0; mi < 2; mi++)
#pragma unroll
            for (int tt = 0; tt < 2; tt++) {
                int R = mw * 32 + mi * 16 + crow;
                int cc = tt * 8 + ccol2;
                *(float2*)&Pb[nw * 1024 + R * 16 + cc] =
                    make_float2(accP[mi][tt][0], accP[mi][tt][1]);
                *(float2*)&Pb[nw * 1024 + (R + 8) * 16 + cc] =
                    make_float2(accP[mi][tt][2], accP[mi][tt][3]);
            }
        __syncthreads();

        float4 o = *(float4*)&Pb[0 * 1024 + prow * 16 + jq * 4];
        float4 p1 = *(float4*)&Pb[1 * 1024 + prow * 16 + jq * 4];
        float4 p2 = *(float4*)&Pb[2 * 1024 + prow * 16 + jq * 4];
        float4 p3 = *(float4*)&Pb[3 * 1024 + prow * 16 + jq * 4];
        o.x += p1.x + p2.x + p3.x;
        o.y += p1.y + p2.y + p3.y;
        o.z += p1.z + p2.z + p3.z;
        o.w += p1.w + p2.w + p3.w;
        if (row0 + prow < Nn) {
            uint2 h = make_uint2(pack_h2(o.x, o.y), pack_h2(o.z, o.w));
            *(uint2*)&Gp[(size_t)(row0 + prow) * 8 + jq * 2] = h;
        }
        __syncthreads();   // Pb reads done before next tile's conversion writes
    }
}

// ---------------- fused message-passing kernels ----------------
// layer-1: 4 threads/edge; each lane gathers 8B (4 halves) of the fp16 G row,
// converts, and RED.128s fp32 into the sum buffer. Degree counted by lane 0.
__global__ void scatter_l1_k(const int* __restrict__ r_src, const int* __restrict__ r_dst, int Er,
                             const int* __restrict__ di_src, const int* __restrict__ di_dst, int Edi,
                             const int* __restrict__ rb_src, const int* __restrict__ rb_dst, int Erb,
                             const int* __restrict__ db_src, const int* __restrict__ db_dst, int Edb) {
    int t = blockIdx.x * blockDim.x + threadIdx.x;
    int e = t >> 2, q = t & 3;
    const uint32_t* g; float4* sum; int* deg; const int* src; const int* dst;
    if (e < Er) {
        g = d_gu; sum = (float4*)d_sr;  deg = d_deg_r;  src = r_src;  dst = r_dst;
    } else if ((e -= Er) < Edi) {
        g = d_gd; sum = (float4*)d_sdi; deg = d_deg_di; src = di_src; dst = di_dst;
    } else if ((e -= Edi) < Erb) {
        g = d_gm; sum = (float4*)d_au;  deg = d_deg_rb; src = rb_src; dst = rb_dst;
    } else if ((e -= Erb) < Edb) {
        g = d_gm; sum = (float4*)d_ad;  deg = d_deg_db; src = db_src; dst = db_dst;
    } else return;
    int s = __ldg(&src[e]);
    int d = __ldg(&dst[e]);
    uint2 h = __ldg((const uint2*)&g[(size_t)s * 8 + q * 2]);
    float2 f0 = unpack_h2(h.x), f1 = unpack_h2(h.y);
    float4 v = make_float4(f0.x, f0.y, f1.x, f1.y);
    atomicAdd(&sum[(size_t)d * 4 + q], v);
    if (q == 0) atomicAdd(&deg[d], 1);
}
// g = ALPHA*g + sum/deg (fp16 store); zero sums + ALL degree counters; write
// movie out base (fp32) and the precomputed 0.5/deg scales for layer-2.
__global__ void update_all_k(const float4* __restrict__ bout4, float4* __restrict__ out) {
    int i = blockIdx.x * blockDim.x + threadIdx.x;
    if (i < NU * 4) {
        int node = i >> 2, q = i & 3;
        uint2 h = *(uint2*)&d_gu[(size_t)node * 8 + q * 2];
        float2 g0 = unpack_h2(h.x), g1 = unpack_h2(h.y);
        float4 av = ((float4*)d_au)[i];
        int dg = d_deg_rb[node];
        float inv = 1.0f / (float)(dg > 0 ? dg : 1);
        g0.x = ALPHA * g0.x + av.x * inv; g0.y = ALPHA * g0.y + av.y * inv;
        g1.x = ALPHA * g1.x + av.z * inv; g1.y = ALPHA * g1.y + av.w * inv;
        *(uint2*)&d_gu[(size_t)node * 8 + q * 2] =
            make_uint2(pack_h2(g0.x, g0.y), pack_h2(g1.x, g1.y));
        ((float4*)d_au)[i] = make_float4(0.f, 0.f, 0.f, 0.f);
        if (q == 0) d_deg_rb[node] = 0;
    } else if (i < (NU + NM) * 4) {
        int idx = i - NU * 4;
        int node = idx >> 2, q = idx & 3;
        uint2 h = *(uint2*)&d_gm[(size_t)node * 8 + q * 2];
        float2 g0 = unpack_h2(h.x), g1 = unpack_h2(h.y);
        float4 s1 = ((float4*)d_sr)[idx], s2 = ((float4*)d_sdi)[idx];
        int dg1 = d_deg_r[node], dg2 = d_deg_di[node];
        float i1 = 0.5f / (float)(dg1 > 0 ? dg1 : 1);
        float i2 = 0.5f / (float)(dg2 > 0 ? dg2 : 1);
        g0.x = ALPHA * g0.x + s1.x * i1 + s2.x * i2;
        g0.y = ALPHA * g0.y + s1.y * i1 + s2.y * i2;
        g1.x = ALPHA * g1.x + s1.z * i1 + s2.z * i2;
        g1.y = ALPHA * g1.y + s1.w * i1 + s2.w * i2;
        *(uint2*)&d_gm[(size_t)node * 8 + q * 2] =
            make_uint2(pack_h2(g0.x, g0.y), pack_h2(g1.x, g1.y));
        ((float4*)d_sr)[idx] = make_float4(0.f, 0.f, 0.f, 0.f);
        ((float4*)d_sdi)[idx] = make_float4(0.f, 0.f, 0.f, 0.f);
        float4 bv = __ldg(&bout4[q]);
        float4 o;
        o.x = ALPHA * g0.x + bv.x;
        o.y = ALPHA * g0.y + bv.y;
        o.z = ALPHA * g1.x + bv.z;
        o.w = ALPHA * g1.y + bv.w;
        out[idx] = o;
        if (q == 0) {
            d_invr[node] = i1; d_invdi[node] = i2;
            d_deg_r[node] = 0; d_deg_di[node] = 0;
        }
    } else if (i < (NU + NM + ND) * 4) {
        int idx = i - (NU + NM) * 4;
        int node = idx >> 2, q = idx & 3;
        uint2 h = *(uint2*)&d_gd[(size_t)node * 8 + q * 2];
        float2 g0 = unpack_h2(h.x), g1 = unpack_h2(h.y);
        float4 av = ((float4*)d_ad)[idx];
        int dg = d_deg_db[node];
        float inv = 1.0f / (float)(dg > 0 ? dg : 1);
        g0.x = ALPHA * g0.x + av.x * inv; g0.y = ALPHA * g0.y + av.y * inv;
        g1.x = ALPHA * g1.x + av.z * inv; g1.y = ALPHA * g1.y + av.w * inv;
        *(uint2*)&d_gd[(size_t)node * 8 + q * 2] =
            make_uint2(pack_h2(g0.x, g0.y), pack_h2(g1.x, g1.y));
        ((float4*)d_ad)[idx] = make_float4(0.f, 0.f, 0.f, 0.f);
        if (q == 0) d_deg_db[node] = 0;
    }
}
// layer-2: 4 threads/edge, fp16 gather, scaled fp32 adds directly into output
__global__ void scatter_l2_k(const int* __restrict__ r_src, const int* __restrict__ r_dst, int Er,
                             const int* __restrict__ di_src, const int* __restrict__ di_dst, int Edi,
                             float4* __restrict__ out) {
    int t = blockIdx.x * blockDim.x + threadIdx.x;
    int e = t >> 2, q = t & 3;
    const uint32_t* g; const int* src; const int* dst; const float* inv;
    if (e < Er) {
        g = d_gu; src = r_src; dst = r_dst; inv = d_invr;
    } else if ((e -= Er) < Edi) {
        g = d_gd; src = di_src; dst = di_dst; inv = d_invdi;
    } else return;
    int s = __ldg(&src[e]);
    int d = __ldg(&dst[e]);
    float sc = __ldg(&inv[d]);
    uint2 h = __ldg((const uint2*)&g[(size_t)s * 8 + q * 2]);
    float2 f0 = unpack_h2(h.x), f1 = unpack_h2(h.y);
    float4 v = make_float4(f0.x * sc, f0.y * sc, f1.x * sc, f1.y * sc);
    atomicAdd(&out[(size_t)d * 4 + q], v);
}

// ---------------- host launch ----------------
extern "C" void kernel_launch(void* const* d_in, const int* in_sizes, int n_in,
                              void* d_out, int out_size) {
    const float *x_u, *x_m, *x_d, *W_u, *b_u, *W_m, *b_m, *W_d, *b_d, *W_o, *b_o;
    const int *r_src, *r_dst, *rb_src, *rb_dst, *di_src, *di_dst, *db_src, *db_dst;
    int Er, Erb, Edi, Edb;

    if (in_sizes[3] == 128 * 128) {
        x_u = (const float*)d_in[0];  x_m = (const float*)d_in[1];  x_d = (const float*)d_in[2];
        W_u = (const float*)d_in[3];  b_u = (const float*)d_in[4];
        W_m = (const float*)d_in[5];  b_m = (const float*)d_in[6];
        W_d = (const float*)d_in[7];  b_d = (const float*)d_in[8];
        W_o = (const float*)d_in[9];  b_o = (const float*)d_in[10];
        r_src = (const int*)d_in[11]; r_dst = (const int*)d_in[12];
        rb_src = (const int*)d_in[13]; rb_dst = (const int*)d_in[14];
        di_src = (const int*)d_in[15]; di_dst = (const int*)d_in[16];
        db_src = (const int*)d_in[17]; db_dst = (const int*)d_in[18];
        Er = in_sizes[11]; Erb = in_sizes[13]; Edi = in_sizes[15]; Edb = in_sizes[17];
    } else {
        x_u = (const float*)d_in[0];  x_m = (const float*)d_in[1];  x_d = (const float*)d_in[2];
        r_src = (const int*)d_in[3];  r_dst = (const int*)d_in[4];
        rb_src = (const int*)d_in[5]; rb_dst = (const int*)d_in[6];
        di_src = (const int*)d_in[7]; di_dst = (const int*)d_in[8];
        db_src = (const int*)d_in[9]; db_dst = (const int*)d_in[10];
        W_u = (const float*)d_in[11]; b_u = (const float*)d_in[12];
        W_m = (const float*)d_in[13]; b_m = (const float*)d_in[14];
        W_d = (const float*)d_in[15]; b_d = (const float*)d_in[16];
        W_o = (const float*)d_in[17]; b_o = (const float*)d_in[18];
        Er = in_sizes[3]; Erb = in_sizes[5]; Edi = in_sizes[7]; Edb = in_sizes[9];
    }

    uint32_t *gu, *gm, *gd;
    cudaGetSymbolAddress((void**)&gu, d_gu);
    cudaGetSymbolAddress((void**)&gm, d_gm);
    cudaGetSymbolAddress((void**)&gd, d_gd);

    cudaFuncSetAttribute(gemm_all, cudaFuncAttributeMaxDynamicSharedMemorySize, SM_TOTAL);

    const int T = 256;
    const int Etot = Er + Edi + Erb + Edb;

    // 0) one persistent GEMM for all three node types (fp16 G output)
    gemm_all<<<GEMM_GRID, 256, SM_TOTAL>>>(
        (const float4*)x_u, (const float4*)x_m, (const float4*)x_d,
        (const float4*)W_u, (const float4*)W_m, (const float4*)W_d,
        b_u, b_m, b_d, W_o, gu, gm, gd);

    // 1) layer-1 raw-sum scatters + degree counting (4 threads/edge, fp16 gathers)
    scatter_l1_k<<<(Etot * 4 + T - 1) / T, T>>>(r_src, r_dst, Er, di_src, di_dst, Edi,
                                                rb_src, rb_dst, Erb, db_src, db_dst, Edb);
    // 2) update + movie output base + layer-2 scales + counter re-zero
    update_all_k<<<((NU + NM + ND) * 4 + T - 1) / T, T>>>((const float4*)b_o, (float4*)d_out);
    // 3) layer-2 scatters add directly into the output (4 threads/edge, fp16 gathers)
    scatter_l2_k<<<((Er + Edi) * 4 + T - 1) / T, T>>>(r_src, r_dst, Er, di_src, di_dst, Edi,
                                                      (float4*)d_out);
}

// round 14
// speedup vs baseline: 1.2642x; 1.0094x over previous
#include <cuda_runtime.h>
#include <cuda_fp16.h>
#include <cstdint>

#define NU 200000
#define NM 100000
#define ND 20000
#define ALPHA 0.01f

#define T0_TILES 3125              // ceil(NU/64)
#define T1_TILES 1563              // ceil(NM/64)
#define T2_TILES 313               // ceil(ND/64)
#define TB1 T0_TILES
#define TB2 (T0_TILES + T1_TILES)
#define TT  (T0_TILES + T1_TILES + T2_TILES)   // 5001

// ---------------- persistent device scratch (zero-initialized at load) ----------------
// G features stored as fp16 (half2-packed): 8 uint32 per node row (16 halves).
__device__ uint32_t d_gu[NU * 8];
__device__ uint32_t d_gm[NM * 8];
__device__ uint32_t d_gd[ND * 8];
__device__ float d_au[NU * 16];   // raw-sum buffers (fp32): zero at entry/exit invariant
__device__ float d_ad[ND * 16];
__device__ float d_sr[NM * 16];   // movie sums from 'rates'
__device__ float d_sdi[NM * 16];  // movie sums from 'dir'
__device__ int   d_deg_r[NM];     // degree counters: zero at entry/exit invariant
__device__ int   d_deg_di[NM];
__device__ int   d_deg_rb[NU];
__device__ int   d_deg_db[ND];
__device__ float d_invr[NM];      // 0.5/deg scales for layer-2 (written by update_all)
__device__ float d_invdi[NM];

// ---------------- helpers ----------------
__device__ __forceinline__ uint32_t smem_u32(const void* p) {
    uint32_t a;
    asm("{ .reg .u64 t; cvta.to.shared.u64 t, %1; cvt.u32.u64 %0, t; }" : "=r"(a) : "l"(p));
    return a;
}
__device__ __forceinline__ void ldmx4(uint32_t& a0, uint32_t& a1, uint32_t& a2, uint32_t& a3,
                                      uint32_t addr) {
    asm volatile("ldmatrix.sync.aligned.m8n8.x4.shared.b16 {%0,%1,%2,%3}, [%4];"
                 : "=r"(a0), "=r"(a1), "=r"(a2), "=r"(a3) : "r"(addr));
}
__device__ __forceinline__ void mma_h(float& c0, float& c1, float& c2, float& c3,
                                      uint32_t a0, uint32_t a1, uint32_t a2, uint32_t a3,
                                      uint32_t b0, uint32_t b1) {
    asm volatile("mma.sync.aligned.m16n8k16.row.col.f32.f16.f16.f32 "
                 "{%0,%1,%2,%3}, {%4,%5,%6,%7}, {%8,%9}, {%0,%1,%2,%3};"
                 : "+f"(c0), "+f"(c1), "+f"(c2), "+f"(c3)
                 : "r"(a0), "r"(a1), "r"(a2), "r"(a3), "r"(b0), "r"(b1));
}
__device__ __forceinline__ uint32_t pack_h2(float x, float y) {
    __half2 h = __floats2half2_rn(x, y);
    return *(uint32_t*)&h;
}
__device__ __forceinline__ float2 unpack_h2(uint32_t u) {
    return __half22float2(*(__half2*)&u);
}
__device__ __forceinline__ void cp16(uint32_t dst, const void* src, int pbytes) {
    asm volatile("cp.async.cg.shared.global [%0], [%1], 16, %2;"
                 :: "r"(dst), "l"(src), "r"(pbytes));
}
#define CP_COMMIT() asm volatile("cp.async.commit_group;" ::: "memory")
#define CP_WAIT0()  asm volatile("cp.async.wait_group 0;" ::: "memory")

// ---------------- persistent fused GEMM over all 3 node types ----------------
// G(fp16) = relu(X @ W^T + b) @ Wout^T. fp16 hi-only A/B/H/Wout.
// cp.async double-buffers raw X. Pb is a DEDICATED buffer (no A alias) ->
// only 3 syncthreads per tile.
// smem: A[64][136]h @0 (17408) | B[128][136]h @17408 (34816) | RAW f32 @52224 (32768)
//       Pb[4][64][16]f32 @84992 (16384)
#define PDA 136
#define OFF_A   0
#define OFF_B   17408
#define OFF_RAW 52224
#define OFF_PB  84992
#define SM_TOTAL 101376
#define GEMM_GRID 296

__global__ void __launch_bounds__(256, 2)
gemm_all(const float4* __restrict__ Xu, const float4* __restrict__ Xm,
         const float4* __restrict__ Xd,
         const float4* __restrict__ Wu, const float4* __restrict__ Wm,
         const float4* __restrict__ Wd,
         const float* __restrict__ bu, const float* __restrict__ bm,
         const float* __restrict__ bd,
         const float* __restrict__ Wout,
         uint32_t* __restrict__ Gu, uint32_t* __restrict__ Gm, uint32_t* __restrict__ Gd) {
    extern __shared__ __align__(16) char smem[];
    const uint32_t sb = smem_u32(smem);
    const int tid = threadIdx.x;
    const int wid = tid >> 5;
    const int lane = tid & 31;

    const int t0 = (int)(((long long)blockIdx.x * TT) / GEMM_GRID);
    const int t1 = (int)(((long long)(blockIdx.x + 1) * TT) / GEMM_GRID);

    const int mw = wid >> 2;
    const int nw = wid & 3;
    const int a_r = (lane & 15);
    const int a_k8 = (lane >> 4) * 8;
    const int b_r = (lane & 7) + ((lane >> 4) << 3);
    const int b_k8 = ((lane >> 3) & 1) * 8;
    const int crow = lane >> 2;
    const int ccol2 = (lane & 3) * 2;
    const int prow = tid >> 2;
    const int jq = tid & 3;

    // ---- Wout B-fragments (fp16 hi) — ONCE ----
    uint32_t wo[2][2][2];
    {
        const int wn = lane >> 2;
#pragma unroll
        for (int kl = 0; kl < 2; kl++)
#pragma unroll
            for (int t = 0; t < 2; t++) {
                const float* wr = Wout + (size_t)(t * 8 + wn) * 128 + nw * 32 + kl * 16;
                wo[kl][t][0] = pack_h2(wr[ccol2], wr[ccol2 + 1]);
                wo[kl][t][1] = pack_h2(wr[8 + ccol2], wr[9 + ccol2]);
            }
    }

    float* Pb = (float*)(smem + OFF_PB);
    float2 biasr[4];
    int curtype = -1;

    // ---- preamble: prefetch raw X for first tile ----
    {
        int t = t0;
        int ty = (t >= TB2) ? 2 : (t >= TB1) ? 1 : 0;
        int lt = t - (ty == 2 ? TB2 : ty == 1 ? TB1 : 0);
        const float4* Xp = (ty == 0) ? Xu : (ty == 1) ? Xm : Xd;
        int Nn = (ty == 0) ? NU : (ty == 1) ? NM : ND;
        int row0 = lt * 64;
#pragma unroll
        for (int u = 0; u < 8; u++) {
            int idx = tid + u * 256;
            int row = row0 + (idx >> 5);
            int ok = row < Nn;
            const float4* src = Xp + (size_t)(ok ? row : 0) * 32 + (idx & 31);
            cp16(sb + OFF_RAW + idx * 16, src, ok ? 16 : 0);
        }
        CP_COMMIT();
    }

    for (int t = t0; t < t1; t++) {
        const int ty = (t >= TB2) ? 2 : (t >= TB1) ? 1 : 0;
        const int lt = t - (ty == 2 ? TB2 : ty == 1 ? TB1 : 0);
        const int Nn = (ty == 0) ? NU : (ty == 1) ? NM : ND;
        uint32_t* Gp = (ty == 0) ? Gu : (ty == 1) ? Gm : Gd;
        const int row0 = lt * 64;

        if (ty != curtype) {
            const float4* Wp = (ty == 0) ? Wu : (ty == 1) ? Wm : Wd;
            const float* bp = (ty == 0) ? bu : (ty == 1) ? bm : bd;
#pragma unroll
            for (int u = 0; u < 16; u++) {
                int idx = tid + u * 256;
                int row = idx >> 5, q4 = idx & 31;
                float4 v = Wp[(size_t)row * 32 + q4];
                uint32_t h0 = pack_h2(v.x, v.y);
                uint32_t h1 = pack_h2(v.z, v.w);
                *(uint2*)(smem + OFF_B + (row * PDA + q4 * 4) * 2) = make_uint2(h0, h1);
            }
#pragma unroll
            for (int ni = 0; ni < 4; ni++)
                biasr[ni] = *(const float2*)&bp[nw * 32 + ni * 8 + ccol2];
            curtype = ty;
        }

        CP_WAIT0();
        __syncthreads();                 // (1) raw(t) + B visible, prev Pb reads done

        // ---- convert raw fp32 -> A fp16 (hi only) ----
#pragma unroll
        for (int u = 0; u < 8; u++) {
            int idx = tid + u * 256;
            int row = idx >> 5, q4 = idx & 31;
            float4 v = ((const float4*)(smem + OFF_RAW))[idx];
            uint32_t h0 = pack_h2(v.x, v.y);
            uint32_t h1 = pack_h2(v.z, v.w);
            *(uint2*)(smem + OFF_A + (row * PDA + q4 * 4) * 2) = make_uint2(h0, h1);
        }
        __syncthreads();                 // (2) A ready; raw buffer free

        // ---- prefetch next tile's raw X (overlaps MMA) ----
        if (t + 1 < t1) {
            int tn = t + 1;
            int tyn = (tn >= TB2) ? 2 : (tn >= TB1) ? 1 : 0;
            int ltn = tn - (tyn == 2 ? TB2 : tyn == 1 ? TB1 : 0);
            const float4* Xn = (tyn == 0) ? Xu : (tyn == 1) ? Xm : Xd;
            int Nx = (tyn == 0) ? NU : (tyn == 1) ? NM : ND;
            int r0n = ltn * 64;
#pragma unroll
            for (int u = 0; u < 8; u++) {
                int idx = tid + u * 256;
                int row = r0n + (idx >> 5);
                int ok = row < Nx;
                const float4* src = Xn + (size_t)(ok ? row : 0) * 32 + (idx & 31);
                cp16(sb + OFF_RAW + idx * 16, src, ok ? 16 : 0);
            }
            CP_COMMIT();
        }

        // ---- MMA mainloop: acc = A @ B^T ----
        float acc[2][4][4];
#pragma unroll
        for (int mi = 0; mi < 2; mi++)
#pragma unroll
            for (int ni = 0; ni < 4; ni++)
#pragma unroll
                for (int e = 0; e < 4; e++) acc[mi][ni][e] = 0.0f;

#pragma unroll 4
        for (int k16 = 0; k16 < 8; k16++) {
            const int k0 = k16 * 16;
            uint32_t ah[2][4], bb[2][4];
#pragma unroll
            for (int mi = 0; mi < 2; mi++) {
                int row = mw * 32 + mi * 16 + a_r;
                uint32_t off = (uint32_t)(row * PDA + k0 + a_k8) * 2;
                ldmx4(ah[mi][0], ah[mi][1], ah[mi][2], ah[mi][3], sb + OFF_A + off);
            }
#pragma unroll
            for (int np = 0; np < 2; np++) {
                int row = nw * 32 + np * 16 + b_r;
                uint32_t off = (uint32_t)(row * PDA + k0 + b_k8) * 2;
                ldmx4(bb[np][0], bb[np][1], bb[np][2], bb[np][3], sb + OFF_B + off);
            }
#pragma unroll
            for (int mi = 0; mi < 2; mi++)
#pragma unroll
                for (int ni = 0; ni < 4; ni++) {
                    int np = ni >> 1, half = (ni & 1) * 2;
                    float* c = acc[mi][ni];
                    mma_h(c[0], c[1], c[2], c[3],
                          ah[mi][0], ah[mi][1], ah[mi][2], ah[mi][3],
                          bb[np][half], bb[np][half + 1]);
                }
        }
        // (no barrier: Pb is dedicated, A stays intact until next tile's convert)

        // ---- bias + relu in regs; tensor-core projection (H hi, Wout hi) ----
        float accP[2][2][4];
#pragma unroll
        for (int mi = 0; mi < 2; mi++)
#pragma unroll
            for (int tt = 0; tt < 2; tt++)
#pragma unroll
                for (int e = 0; e < 4; e++) accP[mi][tt][e] = 0.0f;

#pragma unroll
        for (int mi = 0; mi < 2; mi++) {
#pragma unroll
            for (int ni = 0; ni < 4; ni++) {
                float* c = acc[mi][ni];
                c[0] = fmaxf(c[0] + biasr[ni].x, 0.0f);
                c[1] = fmaxf(c[1] + biasr[ni].y, 0.0f);
                c[2] = fmaxf(c[2] + biasr[ni].x, 0.0f);
                c[3] = fmaxf(c[3] + biasr[ni].y, 0.0f);
            }
#pragma unroll
            for (int kl = 0; kl < 2; kl++) {
                float* L = acc[mi][2 * kl];
                float* R = acc[mi][2 * kl + 1];
                uint32_t a0 = pack_h2(L[0], L[1]);
                uint32_t a1 = pack_h2(L[2], L[3]);
                uint32_t a2 = pack_h2(R[0], R[1]);
                uint32_t a3 = pack_h2(R[2], R[3]);
#pragma unroll
                for (int tt = 0; tt < 2; tt++) {
                    float* p = accP[mi][tt];
                    mma_h(p[0], p[1], p[2], p[3], a0, a1, a2, a3,
                          wo[kl][tt][0], wo[kl][tt][1]);
                }
            }
        }

        // ---- write per-warp partials, k-reduce across the 4 nw warps ----
#pragma unroll
        for (int mi = 0; mi < 2; mi++)
#pragma unroll
            for (int tt = 0; tt < 2; tt++) {
                int R = mw * 32 + mi * 16 + crow;
                int cc = tt * 8 + ccol2;
                *(float2*)&Pb[nw * 1024 + R * 16 + cc] =
                    make_float2(accP[mi][tt][0], accP[mi][tt][1]);
                *(float2*)&Pb[nw * 1024 + (R + 8) * 16 + cc] =
                    make_float2(accP[mi][tt][2], accP[mi][tt][3]);
            }
        __syncthreads();                 // (3) Pb complete (implies all A reads done)

        float4 o = *(float4*)&Pb[0 * 1024 + prow * 16 + jq * 4];
        float4 p1 = *(float4*)&Pb[1 * 1024 + prow * 16 + jq * 4];
        float4 p2 = *(float4*)&Pb[2 * 1024 + prow * 16 + jq * 4];
        float4 p3 = *(float4*)&Pb[3 * 1024 + prow * 16 + jq * 4];
        o.x += p1.x + p2.x + p3.x;
        o.y += p1.y + p2.y + p3.y;
        o.z += p1.z + p2.z + p3.z;
        o.w += p1.w + p2.w + p3.w;
        if (row0 + prow < Nn) {
            uint2 h = make_uint2(pack_h2(o.x, o.y), pack_h2(o.z, o.w));
            *(uint2*)&Gp[(size_t)(row0 + prow) * 8 + jq * 2] = h;
        }
        // no loop-end barrier: sync (1) next iteration orders Pb reads
        // before the next Pb writes (which follow sync (3) of that tile).
    }
}

// ---------------- fused message-passing kernels ----------------
// layer-1: 4 threads/edge; each lane gathers 8B (4 halves) of the fp16 G row,
// converts, and RED.128s fp32 into the sum buffer. Degree counted by lane 0.
__global__ void scatter_l1_k(const int* __restrict__ r_src, const int* __restrict__ r_dst, int Er,
                             const int* __restrict__ di_src, const int* __restrict__ di_dst, int Edi,
                             const int* __restrict__ rb_src, const int* __restrict__ rb_dst, int Erb,
                             const int* __restrict__ db_src, const int* __restrict__ db_dst, int Edb) {
    int t = blockIdx.x * blockDim.x + threadIdx.x;
    int e = t >> 2, q = t & 3;
    const uint32_t* g; float4* sum; int* deg; const int* src; const int* dst;
    if (e < Er) {
        g = d_gu; sum = (float4*)d_sr;  deg = d_deg_r;  src = r_src;  dst = r_dst;
    } else if ((e -= Er) < Edi) {
        g = d_gd; sum = (float4*)d_sdi; deg = d_deg_di; src = di_src; dst = di_dst;
    } else if ((e -= Edi) < Erb) {
        g = d_gm; sum = (float4*)d_au;  deg = d_deg_rb; src = rb_src; dst = rb_dst;
    } else if ((e -= Erb) < Edb) {
        g = d_gm; sum = (float4*)d_ad;  deg = d_deg_db; src = db_src; dst = db_dst;
    } else return;
    int s = __ldg(&src[e]);
    int d = __ldg(&dst[e]);
    uint2 h = __ldg((const uint2*)&g[(size_t)s * 8 + q * 2]);
    float2 f0 = unpack_h2(h.x), f1 = unpack_h2(h.y);
    float4 v = make_float4(f0.x, f0.y, f1.x, f1.y);
    atomicAdd(&sum[(size_t)d * 4 + q], v);
    if (q == 0) atomicAdd(&deg[d], 1);
}
// g = ALPHA*g + sum/deg (fp16 store); zero sums + ALL degree counters; write
// movie out base (fp32) and the precomputed 0.5/deg scales for layer-2.
__global__ void update_all_k(const float4* __restrict__ bout4, float4* __restrict__ out) {
    int i = blockIdx.x * blockDim.x + threadIdx.x;
    if (i < NU * 4) {
        int node = i >> 2, q = i & 3;
        uint2 h = *(uint2*)&d_gu[(size_t)node * 8 + q * 2];
        float2 g0 = unpack_h2(h.x), g1 = unpack_h2(h.y);
        float4 av = ((float4*)d_au)[i];
        int dg = d_deg_rb[node];
        float inv = 1.0f / (float)(dg > 0 ? dg : 1);
        g0.x = ALPHA * g0.x + av.x * inv; g0.y = ALPHA * g0.y + av.y * inv;
        g1.x = ALPHA * g1.x + av.z * inv; g1.y = ALPHA * g1.y + av.w * inv;
        *(uint2*)&d_gu[(size_t)node * 8 + q * 2] =
            make_uint2(pack_h2(g0.x, g0.y), pack_h2(g1.x, g1.y));
        ((float4*)d_au)[i] = make_float4(0.f, 0.f, 0.f, 0.f);
        if (q == 0) d_deg_rb[node] = 0;
    } else if (i < (NU + NM) * 4) {
        int idx = i - NU * 4;
        int node = idx >> 2, q = idx & 3;
        uint2 h = *(uint2*)&d_gm[(size_t)node * 8 + q * 2];
        float2 g0 = unpack_h2(h.x), g1 = unpack_h2(h.y);
        float4 s1 = ((float4*)d_sr)[idx], s2 = ((float4*)d_sdi)[idx];
        int dg1 = d_deg_r[node], dg2 = d_deg_di[node];
        float i1 = 0.5f / (float)(dg1 > 0 ? dg1 : 1);
        float i2 = 0.5f / (float)(dg2 > 0 ? dg2 : 1);
        g0.x = ALPHA * g0.x + s1.x * i1 + s2.x * i2;
        g0.y = ALPHA * g0.y + s1.y * i1 + s2.y * i2;
        g1.x = ALPHA * g1.x + s1.z * i1 + s2.z * i2;
        g1.y = ALPHA * g1.y + s1.w * i1 + s2.w * i2;
        *(uint2*)&d_gm[(size_t)node * 8 + q * 2] =
            make_uint2(pack_h2(g0.x, g0.y), pack_h2(g1.x, g1.y));
        ((float4*)d_sr)[idx] = make_float4(0.f, 0.f, 0.f, 0.f);
        ((float4*)d_sdi)[idx] = make_float4(0.f, 0.f, 0.f, 0.f);
        float4 bv = __ldg(&bout4[q]);
        float4 o;
        o.x = ALPHA * g0.x + bv.x;
        o.y = ALPHA * g0.y + bv.y;
        o.z = ALPHA * g1.x + bv.z;
        o.w = ALPHA * g1.y + bv.w;
        out[idx] = o;
        if (q == 0) {
            d_invr[node] = i1; d_invdi[node] = i2;
            d_deg_r[node] = 0; d_deg_di[node] = 0;
        }
    } else if (i < (NU + NM + ND) * 4) {
        int idx = i - (NU + NM) * 4;
        int node = idx >> 2, q = idx & 3;
        uint2 h = *(uint2*)&d_gd[(size_t)node * 8 + q * 2];
        float2 g0 = unpack_h2(h.x), g1 = unpack_h2(h.y);
        float4 av = ((float4*)d_ad)[idx];
        int dg = d_deg_db[node];
        float inv = 1.0f / (float)(dg > 0 ? dg : 1);
        g0.x = ALPHA * g0.x + av.x * inv; g0.y = ALPHA * g0.y + av.y * inv;
        g1.x = ALPHA * g1.x + av.z * inv; g1.y = ALPHA * g1.y + av.w * inv;
        *(uint2*)&d_gd[(size_t)node * 8 + q * 2] =
            make_uint2(pack_h2(g0.x, g0.y), pack_h2(g1.x, g1.y));
        ((float4*)d_ad)[idx] = make_float4(0.f, 0.f, 0.f, 0.f);
        if (q == 0) d_deg_db[node] = 0;
    }
}
// layer-2: 4 threads/edge, fp16 gather, scaled fp32 adds directly into output
__global__ void scatter_l2_k(const int* __restrict__ r_src, const int* __restrict__ r_dst, int Er,
                             const int* __restrict__ di_src, const int* __restrict__ di_dst, int Edi,
                             float4* __restrict__ out) {
    int t = blockIdx.x * blockDim.x + threadIdx.x;
    int e = t >> 2, q = t & 3;
    const uint32_t* g; const int* src; const int* dst; const float* inv;
    if (e < Er) {
        g = d_gu; src = r_src; dst = r_dst; inv = d_invr;
    } else if ((e -= Er) < Edi) {
        g = d_gd; src = di_src; dst = di_dst; inv = d_invdi;
    } else return;
    int s = __ldg(&src[e]);
    int d = __ldg(&dst[e]);
    float sc = __ldg(&inv[d]);
    uint2 h = __ldg((const uint2*)&g[(size_t)s * 8 + q * 2]);
    float2 f0 = unpack_h2(h.x), f1 = unpack_h2(h.y);
    float4 v = make_float4(f0.x * sc, f0.y * sc, f1.x * sc, f1.y * sc);
    atomicAdd(&out[(size_t)d * 4 + q], v);
}

// ---------------- host launch ----------------
extern "C" void kernel_launch(void* const* d_in, const int* in_sizes, int n_in,
                              void* d_out, int out_size) {
    const float *x_u, *x_m, *x_d, *W_u, *b_u, *W_m, *b_m, *W_d, *b_d, *W_o, *b_o;
    const int *r_src, *r_dst, *rb_src, *rb_dst, *di_src, *di_dst, *db_src, *db_dst;
    int Er, Erb, Edi, Edb;

    if (in_sizes[3] == 128 * 128) {
        x_u = (const float*)d_in[0];  x_m = (const float*)d_in[1];  x_d = (const float*)d_in[2];
        W_u = (const float*)d_in[3];  b_u = (const float*)d_in[4];
        W_m = (const float*)d_in[5];  b_m = (const float*)d_in[6];
        W_d = (const float*)d_in[7];  b_d = (const float*)d_in[8];
        W_o = (const float*)d_in[9];  b_o = (const float*)d_in[10];
        r_src = (const int*)d_in[11]; r_dst = (const int*)d_in[12];
        rb_src = (const int*)d_in[13]; rb_dst = (const int*)d_in[14];
        di_src = (const int*)d_in[15]; di_dst = (const int*)d_in[16];
        db_src = (const int*)d_in[17]; db_dst = (const int*)d_in[18];
        Er = in_sizes[11]; Erb = in_sizes[13]; Edi = in_sizes[15]; Edb = in_sizes[17];
    } else {
        x_u = (const float*)d_in[0];  x_m = (const float*)d_in[1];  x_d = (const float*)d_in[2];
        r_src = (const int*)d_in[3];  r_dst = (const int*)d_in[4];
        rb_src = (const int*)d_in[5]; rb_dst = (const int*)d_in[6];
        di_src = (const int*)d_in[7]; di_dst = (const int*)d_in[8];
        db_src = (const int*)d_in[9]; db_dst = (const int*)d_in[10];
        W_u = (const float*)d_in[11]; b_u = (const float*)d_in[12];
        W_m = (const float*)d_in[13]; b_m = (const float*)d_in[14];
        W_d = (const float*)d_in[15]; b_d = (const float*)d_in[16];
        W_o = (const float*)d_in[17]; b_o = (const float*)d_in[18];
        Er = in_sizes[3]; Erb = in_sizes[5]; Edi = in_sizes[7]; Edb = in_sizes[9];
    }

    uint32_t *gu, *gm, *gd;
    cudaGetSymbolAddress((void**)&gu, d_gu);
    cudaGetSymbolAddress((void**)&gm, d_gm);
    cudaGetSymbolAddress((void**)&gd, d_gd);

    cudaFuncSetAttribute(gemm_all, cudaFuncAttributeMaxDynamicSharedMemorySize, SM_TOTAL);

    const int T = 256;
    const int Etot = Er + Edi + Erb + Edb;

    // 0) one persistent GEMM for all three node types (fp16 G output)
    gemm_all<<<GEMM_GRID, 256, SM_TOTAL>>>(
        (const float4*)x_u, (const float4*)x_m, (const float4*)x_d,
        (const float4*)W_u, (const float4*)W_m, (const float4*)W_d,
        b_u, b_m, b_d, W_o, gu, gm, gd);

    // 1) layer-1 raw-sum scatters + degree counting (4 threads/edge, fp16 gathers)
    scatter_l1_k<<<(Etot * 4 + T - 1) / T, T>>>(r_src, r_dst, Er, di_src, di_dst, Edi,
                                                rb_src, rb_dst, Erb, db_src, db_dst, Edb);
    // 2) update + movie output base + layer-2 scales + counter re-zero
    update_all_k<<<((NU + NM + ND) * 4 + T - 1) / T, T>>>((const float4*)b_o, (float4*)d_out);
    // 3) layer-2 scatters add directly into the output (4 threads/edge, fp16 gathers)
    scatter_l2_k<<<((Er + Edi) * 4 + T - 1) / T, T>>>(r_src, r_dst, Er, di_src, di_dst, Edi,
                                                      (float4*)d_out);
}

// round 15
// speedup vs baseline: 1.3613x; 1.0768x over previous
#include <cuda_runtime.h>
#include <cuda_fp16.h>
#include <cstdint>

#define NU 200000
#define NM 100000
#define ND 20000
#define ALPHA 0.01f

#define T0_TILES 3125              // ceil(NU/64)
#define T1_TILES 1563              // ceil(NM/64)
#define T2_TILES 313               // ceil(ND/64)
#define TB1 T0_TILES
#define TB2 (T0_TILES + T1_TILES)
#define TT  (T0_TILES + T1_TILES + T2_TILES)   // 5001

// ---------------- persistent device scratch (zero-initialized at load) ----------------
// G features fp16 (half2-packed): 8 uint32 per node row (16 halves).
__device__ uint32_t d_gu[NU * 8];
__device__ uint32_t d_gm[NM * 8];
__device__ uint32_t d_gd[ND * 8];
// layer-1 raw-sum buffers now fp16 (half2-packed), zero at entry/exit invariant
__device__ uint32_t d_au[NU * 8];
__device__ uint32_t d_ad[ND * 8];
__device__ uint32_t d_sr[NM * 8];   // movie sums from 'rates'
__device__ uint32_t d_sdi[NM * 8];  // movie sums from 'dir'
__device__ int   d_deg_r[NM];       // degree counters: zero at entry/exit invariant
__device__ int   d_deg_di[NM];
__device__ int   d_deg_rb[NU];
__device__ int   d_deg_db[ND];
__device__ float d_invr[NM];        // 0.5/deg scales for layer-2 (written by update_all)
__device__ float d_invdi[NM];

// ---------------- helpers ----------------
__device__ __forceinline__ uint32_t smem_u32(const void* p) {
    uint32_t a;
    asm("{ .reg .u64 t; cvta.to.shared.u64 t, %1; cvt.u32.u64 %0, t; }" : "=r"(a) : "l"(p));
    return a;
}
__device__ __forceinline__ void ldmx4(uint32_t& a0, uint32_t& a1, uint32_t& a2, uint32_t& a3,
                                      uint32_t addr) {
    asm volatile("ldmatrix.sync.aligned.m8n8.x4.shared.b16 {%0,%1,%2,%3}, [%4];"
                 : "=r"(a0), "=r"(a1), "=r"(a2), "=r"(a3) : "r"(addr));
}
__device__ __forceinline__ void mma_h(float& c0, float& c1, float& c2, float& c3,
                                      uint32_t a0, uint32_t a1, uint32_t a2, uint32_t a3,
                                      uint32_t b0, uint32_t b1) {
    asm volatile("mma.sync.aligned.m16n8k16.row.col.f32.f16.f16.f32 "
                 "{%0,%1,%2,%3}, {%4,%5,%6,%7}, {%8,%9}, {%0,%1,%2,%3};"
                 : "+f"(c0), "+f"(c1), "+f"(c2), "+f"(c3)
                 : "r"(a0), "r"(a1), "r"(a2), "r"(a3), "r"(b0), "r"(b1));
}
__device__ __forceinline__ uint32_t pack_h2(float x, float y) {
    __half2 h = __floats2half2_rn(x, y);
    return *(uint32_t*)&h;
}
__device__ __forceinline__ float2 unpack_h2(uint32_t u) {
    return __half22float2(*(__half2*)&u);
}
// vectorized fp16x2 reduction: adds 8 halves (16B) to global memory
__device__ __forceinline__ void red_v4h2(uint32_t* addr, uint4 v) {
    asm volatile("red.global.add.noftz.v4.f16x2 [%0], {%1,%2,%3,%4};"
                 :: "l"(addr), "r"(v.x), "r"(v.y), "r"(v.z), "r"(v.w) : "memory");
}
__device__ __forceinline__ void cp16(uint32_t dst, const void* src, int pbytes) {
    asm volatile("cp.async.cg.shared.global [%0], [%1], 16, %2;"
                 :: "r"(dst), "l"(src), "r"(pbytes));
}
#define CP_COMMIT() asm volatile("cp.async.commit_group;" ::: "memory")
#define CP_WAIT0()  asm volatile("cp.async.wait_group 0;" ::: "memory")

// ---------------- persistent fused GEMM over all 3 node types ----------------
// (unchanged from R14 — passing baseline)
#define PDA 136
#define OFF_A   0
#define OFF_B   17408
#define OFF_RAW 52224
#define OFF_PB  84992
#define SM_TOTAL 101376
#define GEMM_GRID 296

__global__ void __launch_bounds__(256, 2)
gemm_all(const float4* __restrict__ Xu, const float4* __restrict__ Xm,
         const float4* __restrict__ Xd,
         const float4* __restrict__ Wu, const float4* __restrict__ Wm,
         const float4* __restrict__ Wd,
         const float* __restrict__ bu, const float* __restrict__ bm,
         const float* __restrict__ bd,
         const float* __restrict__ Wout,
         uint32_t* __restrict__ Gu, uint32_t* __restrict__ Gm, uint32_t* __restrict__ Gd) {
    extern __shared__ __align__(16) char smem[];
    const uint32_t sb = smem_u32(smem);
    const int tid = threadIdx.x;
    const int wid = tid >> 5;
    const int lane = tid & 31;

    const int t0 = (int)(((long long)blockIdx.x * TT) / GEMM_GRID);
    const int t1 = (int)(((long long)(blockIdx.x + 1) * TT) / GEMM_GRID);

    const int mw = wid >> 2;
    const int nw = wid & 3;
    const int a_r = (lane & 15);
    const int a_k8 = (lane >> 4) * 8;
    const int b_r = (lane & 7) + ((lane >> 4) << 3);
    const int b_k8 = ((lane >> 3) & 1) * 8;
    const int crow = lane >> 2;
    const int ccol2 = (lane & 3) * 2;
    const int prow = tid >> 2;
    const int jq = tid & 3;

    // ---- Wout B-fragments (fp16 hi) — ONCE ----
    uint32_t wo[2][2][2];
    {
        const int wn = lane >> 2;
#pragma unroll
        for (int kl = 0; kl < 2; kl++)
#pragma unroll
            for (int t = 0; t < 2; t++) {
                const float* wr = Wout + (size_t)(t * 8 + wn) * 128 + nw * 32 + kl * 16;
                wo[kl][t][0] = pack_h2(wr[ccol2], wr[ccol2 + 1]);
                wo[kl][t][1] = pack_h2(wr[8 + ccol2], wr[9 + ccol2]);
            }
    }

    float* Pb = (float*)(smem + OFF_PB);
    float2 biasr[4];
    int curtype = -1;

    // ---- preamble: prefetch raw X for first tile ----
    {
        int t = t0;
        int ty = (t >= TB2) ? 2 : (t >= TB1) ? 1 : 0;
        int lt = t - (ty == 2 ? TB2 : ty == 1 ? TB1 : 0);
        const float4* Xp = (ty == 0) ? Xu : (ty == 1) ? Xm : Xd;
        int Nn = (ty == 0) ? NU : (ty == 1) ? NM : ND;
        int row0 = lt * 64;
#pragma unroll
        for (int u = 0; u < 8; u++) {
            int idx = tid + u * 256;
            int row = row0 + (idx >> 5);
            int ok = row < Nn;
            const float4* src = Xp + (size_t)(ok ? row : 0) * 32 + (idx & 31);
            cp16(sb + OFF_RAW + idx * 16, src, ok ? 16 : 0);
        }
        CP_COMMIT();
    }

    for (int t = t0; t < t1; t++) {
        const int ty = (t >= TB2) ? 2 : (t >= TB1) ? 1 : 0;
        const int lt = t - (ty == 2 ? TB2 : ty == 1 ? TB1 : 0);
        const int Nn = (ty == 0) ? NU : (ty == 1) ? NM : ND;
        uint32_t* Gp = (ty == 0) ? Gu : (ty == 1) ? Gm : Gd;
        const int row0 = lt * 64;

        if (ty != curtype) {
            const float4* Wp = (ty == 0) ? Wu : (ty == 1) ? Wm : Wd;
            const float* bp = (ty == 0) ? bu : (ty == 1) ? bm : bd;
#pragma unroll
            for (int u = 0; u < 16; u++) {
                int idx = tid + u * 256;
                int row = idx >> 5, q4 = idx & 31;
                float4 v = Wp[(size_t)row * 32 + q4];
                uint32_t h0 = pack_h2(v.x, v.y);
                uint32_t h1 = pack_h2(v.z, v.w);
                *(uint2*)(smem + OFF_B + (row * PDA + q4 * 4) * 2) = make_uint2(h0, h1);
            }
#pragma unroll
            for (int ni = 0; ni < 4; ni++)
                biasr[ni] = *(const float2*)&bp[nw * 32 + ni * 8 + ccol2];
            curtype = ty;
        }

        CP_WAIT0();
        __syncthreads();                 // (1) raw(t) + B visible, prev Pb reads done

        // ---- convert raw fp32 -> A fp16 (hi only) ----
#pragma unroll
        for (int u = 0; u < 8; u++) {
            int idx = tid + u * 256;
            int row = idx >> 5, q4 = idx & 31;
            float4 v = ((const float4*)(smem + OFF_RAW))[idx];
            uint32_t h0 = pack_h2(v.x, v.y);
            uint32_t h1 = pack_h2(v.z, v.w);
            *(uint2*)(smem + OFF_A + (row * PDA + q4 * 4) * 2) = make_uint2(h0, h1);
        }
        __syncthreads();                 // (2) A ready; raw buffer free

        // ---- prefetch next tile's raw X (overlaps MMA) ----
        if (t + 1 < t1) {
            int tn = t + 1;
            int tyn = (tn >= TB2) ? 2 : (tn >= TB1) ? 1 : 0;
            int ltn = tn - (tyn == 2 ? TB2 : tyn == 1 ? TB1 : 0);
            const float4* Xn = (tyn == 0) ? Xu : (tyn == 1) ? Xm : Xd;
            int Nx = (tyn == 0) ? NU : (tyn == 1) ? NM : ND;
            int r0n = ltn * 64;
#pragma unroll
            for (int u = 0; u < 8; u++) {
                int idx = tid + u * 256;
                int row = r0n + (idx >> 5);
                int ok = row < Nx;
                const float4* src = Xn + (size_t)(ok ? row : 0) * 32 + (idx & 31);
                cp16(sb + OFF_RAW + idx * 16, src, ok ? 16 : 0);
            }
            CP_COMMIT();
        }

        // ---- MMA mainloop: acc = A @ B^T ----
        float acc[2][4][4];
#pragma unroll
        for (int mi = 0; mi < 2; mi++)
#pragma unroll
            for (int ni = 0; ni < 4; ni++)
#pragma unroll
                for (int e = 0; e < 4; e++) acc[mi][ni][e] = 0.0f;

#pragma unroll 4
        for (int k16 = 0; k16 < 8; k16++) {
            const int k0 = k16 * 16;
            uint32_t ah[2][4], bb[2][4];
#pragma unroll
            for (int mi = 0; mi < 2; mi++) {
                int row = mw * 32 + mi * 16 + a_r;
                uint32_t off = (uint32_t)(row * PDA + k0 + a_k8) * 2;
                ldmx4(ah[mi][0], ah[mi][1], ah[mi][2], ah[mi][3], sb + OFF_A + off);
            }
#pragma unroll
            for (int np = 0; np < 2; np++) {
                int row = nw * 32 + np * 16 + b_r;
                uint32_t off = (uint32_t)(row * PDA + k0 + b_k8) * 2;
                ldmx4(bb[np][0], bb[np][1], bb[np][2], bb[np][3], sb + OFF_B + off);
            }
#pragma unroll
            for (int mi = 0; mi < 2; mi++)
#pragma unroll
                for (int ni = 0; ni < 4; ni++) {
                    int np = ni >> 1, half = (ni & 1) * 2;
                    float* c = acc[mi][ni];
                    mma_h(c[0], c[1], c[2], c[3],
                          ah[mi][0], ah[mi][1], ah[mi][2], ah[mi][3],
                          bb[np][half], bb[np][half + 1]);
                }
        }

        // ---- bias + relu in regs; tensor-core projection (H hi, Wout hi) ----
        float accP[2][2][4];
#pragma unroll
        for (int mi = 0; mi < 2; mi++)
#pragma unroll
            for (int tt = 0; tt < 2; tt++)
#pragma unroll
                for (int e = 0; e < 4; e++) accP[mi][tt][e] = 0.0f;

#pragma unroll
        for (int mi = 0; mi < 2; mi++) {
#pragma unroll
            for (int ni = 0; ni < 4; ni++) {
                float* c = acc[mi][ni];
                c[0] = fmaxf(c[0] + biasr[ni].x, 0.0f);
                c[1] = fmaxf(c[1] + biasr[ni].y, 0.0f);
                c[2] = fmaxf(c[2] + biasr[ni].x, 0.0f);
                c[3] = fmaxf(c[3] + biasr[ni].y, 0.0f);
            }
#pragma unroll
            for (int kl = 0; kl < 2; kl++) {
                float* L = acc[mi][2 * kl];
                float* R = acc[mi][2 * kl + 1];
                uint32_t a0 = pack_h2(L[0], L[1]);
                uint32_t a1 = pack_h2(L[2], L[3]);
                uint32_t a2 = pack_h2(R[0], R[1]);
                uint32_t a3 = pack_h2(R[2], R[3]);
#pragma unroll
                for (int tt = 0; tt < 2; tt++) {
                    float* p = accP[mi][tt];
                    mma_h(p[0], p[1], p[2], p[3], a0, a1, a2, a3,
                          wo[kl][tt][0], wo[kl][tt][1]);
                }
            }
        }

        // ---- write per-warp partials, k-reduce across the 4 nw warps ----
#pragma unroll
        for (int mi = 0; mi < 2; mi++)
#pragma unroll
            for (int tt = 0; tt < 2; tt++) {
                int R = mw * 32 + mi * 16 + crow;
                int cc = tt * 8 + ccol2;
                *(float2*)&Pb[nw * 1024 + R * 16 + cc] =
                    make_float2(accP[mi][tt][0], accP[mi][tt][1]);
                *(float2*)&Pb[nw * 1024 + (R + 8) * 16 + cc] =
                    make_float2(accP[mi][tt][2], accP[mi][tt][3]);
            }
        __syncthreads();                 // (3) Pb complete

        float4 o = *(float4*)&Pb[0 * 1024 + prow * 16 + jq * 4];
        float4 p1 = *(float4*)&Pb[1 * 1024 + prow * 16 + jq * 4];
        float4 p2 = *(float4*)&Pb[2 * 1024 + prow * 16 + jq * 4];
        float4 p3 = *(float4*)&Pb[3 * 1024 + prow * 16 + jq * 4];
        o.x += p1.x + p2.x + p3.x;
        o.y += p1.y + p2.y + p3.y;
        o.z += p1.z + p2.z + p3.z;
        o.w += p1.w + p2.w + p3.w;
        if (row0 + prow < Nn) {
            uint2 h = make_uint2(pack_h2(o.x, o.y), pack_h2(o.z, o.w));
            *(uint2*)&Gp[(size_t)(row0 + prow) * 8 + jq * 2] = h;
        }
    }
}

// ---------------- fused message-passing kernels ----------------
// layer-1: TWO threads/edge; each lane gathers 16B (8 halves) of fp16 G and
// reduces it directly into the fp16 sum buffer with one red.v4.f16x2.
__global__ void scatter_l1_k(const int* __restrict__ r_src, const int* __restrict__ r_dst, int Er,
                             const int* __restrict__ di_src, const int* __restrict__ di_dst, int Edi,
                             const int* __restrict__ rb_src, const int* __restrict__ rb_dst, int Erb,
                             const int* __restrict__ db_src, const int* __restrict__ db_dst, int Edb) {
    int t = blockIdx.x * blockDim.x + threadIdx.x;
    int e = t >> 1, q = t & 1;
    const uint32_t* g; uint32_t* sum; int* deg; const int* src; const int* dst;
    if (e < Er) {
        g = d_gu; sum = d_sr;  deg = d_deg_r;  src = r_src;  dst = r_dst;
    } else if ((e -= Er) < Edi) {
        g = d_gd; sum = d_sdi; deg = d_deg_di; src = di_src; dst = di_dst;
    } else if ((e -= Edi) < Erb) {
        g = d_gm; sum = d_au;  deg = d_deg_rb; src = rb_src; dst = rb_dst;
    } else if ((e -= Erb) < Edb) {
        g = d_gm; sum = d_ad;  deg = d_deg_db; src = db_src; dst = db_dst;
    } else return;
    int s = __ldg(&src[e]);
    int d = __ldg(&dst[e]);
    uint4 v = __ldg((const uint4*)&g[(size_t)s * 8 + q * 4]);
    red_v4h2(&sum[(size_t)d * 8 + q * 4], v);
    if (q == 0) atomicAdd(&deg[d], 1);
}
// g = ALPHA*g + sum/deg (fp16 sums); zero sums + ALL degree counters; write
// movie out base (fp32) and the precomputed 0.5/deg scales for layer-2.
__global__ void update_all_k(const float4* __restrict__ bout4, float4* __restrict__ out) {
    int i = blockIdx.x * blockDim.x + threadIdx.x;
    if (i < NU * 4) {
        int node = i >> 2, q = i & 3;
        uint2 h = *(uint2*)&d_gu[(size_t)node * 8 + q * 2];
        float2 g0 = unpack_h2(h.x), g1 = unpack_h2(h.y);
        uint2 a = *(uint2*)&d_au[(size_t)node * 8 + q * 2];
        float2 a0 = unpack_h2(a.x), a1 = unpack_h2(a.y);
        int dg = d_deg_rb[node];
        float inv = 1.0f / (float)(dg > 0 ? dg : 1);
        g0.x = ALPHA * g0.x + a0.x * inv; g0.y = ALPHA * g0.y + a0.y * inv;
        g1.x = ALPHA * g1.x + a1.x * inv; g1.y = ALPHA * g1.y + a1.y * inv;
        *(uint2*)&d_gu[(size_t)node * 8 + q * 2] =
            make_uint2(pack_h2(g0.x, g0.y), pack_h2(g1.x, g1.y));
        *(uint2*)&d_au[(size_t)node * 8 + q * 2] = make_uint2(0u, 0u);
        if (q == 0) d_deg_rb[node] = 0;
    } else if (i < (NU + NM) * 4) {
        int idx = i - NU * 4;
        int node = idx >> 2, q = idx & 3;
        uint2 h = *(uint2*)&d_gm[(size_t)node * 8 + q * 2];
        float2 g0 = unpack_h2(h.x), g1 = unpack_h2(h.y);
        uint2 u1 = *(uint2*)&d_sr[(size_t)node * 8 + q * 2];
        uint2 u2 = *(uint2*)&d_sdi[(size_t)node * 8 + q * 2];
        float2 s1a = unpack_h2(u1.x), s1b = unpack_h2(u1.y);
        float2 s2a = unpack_h2(u2.x), s2b = unpack_h2(u2.y);
        int dg1 = d_deg_r[node], dg2 = d_deg_di[node];
        float i1 = 0.5f / (float)(dg1 > 0 ? dg1 : 1);
        float i2 = 0.5f / (float)(dg2 > 0 ? dg2 : 1);
        g0.x = ALPHA * g0.x + s1a.x * i1 + s2a.x * i2;
        g0.y = ALPHA * g0.y + s1a.y * i1 + s2a.y * i2;
        g1.x = ALPHA * g1.x + s1b.x * i1 + s2b.x * i2;
        g1.y = ALPHA * g1.y + s1b.y * i1 + s2b.y * i2;
        *(uint2*)&d_gm[(size_t)node * 8 + q * 2] =
            make_uint2(pack_h2(g0.x, g0.y), pack_h2(g1.x, g1.y));
        *(uint2*)&d_sr[(size_t)node * 8 + q * 2] = make_uint2(0u, 0u);
        *(uint2*)&d_sdi[(size_t)node * 8 + q * 2] = make_uint2(0u, 0u);
        float4 bv = __ldg(&bout4[q]);
        float4 o;
        o.x = ALPHA * g0.x + bv.x;
        o.y = ALPHA * g0.y + bv.y;
        o.z = ALPHA * g1.x + bv.z;
        o.w = ALPHA * g1.y + bv.w;
        out[idx] = o;
        if (q == 0) {
            d_invr[node] = i1; d_invdi[node] = i2;
            d_deg_r[node] = 0; d_deg_di[node] = 0;
        }
    } else if (i < (NU + NM + ND) * 4) {
        int idx = i - (NU + NM) * 4;
        int node = idx >> 2, q = idx & 3;
        uint2 h = *(uint2*)&d_gd[(size_t)node * 8 + q * 2];
        float2 g0 = unpack_h2(h.x), g1 = unpack_h2(h.y);
        uint2 a = *(uint2*)&d_ad[(size_t)node * 8 + q * 2];
        float2 a0 = unpack_h2(a.x), a1 = unpack_h2(a.y);
        int dg = d_deg_db[node];
        float inv = 1.0f / (float)(dg > 0 ? dg : 1);
        g0.x = ALPHA * g0.x + a0.x * inv; g0.y = ALPHA * g0.y + a0.y * inv;
        g1.x = ALPHA * g1.x + a1.x * inv; g1.y = ALPHA * g1.y + a1.y * inv;
        *(uint2*)&d_gd[(size_t)node * 8 + q * 2] =
            make_uint2(pack_h2(g0.x, g0.y), pack_h2(g1.x, g1.y));
        *(uint2*)&d_ad[(size_t)node * 8 + q * 2] = make_uint2(0u, 0u);
        if (q == 0) d_deg_db[node] = 0;
    }
}
// layer-2: 4 threads/edge, fp16 gather, scaled fp32 adds directly into output
__global__ void scatter_l2_k(const int* __restrict__ r_src, const int* __restrict__ r_dst, int Er,
                             const int* __restrict__ di_src, const int* __restrict__ di_dst, int Edi,
                             float4* __restrict__ out) {
    int t = blockIdx.x * blockDim.x + threadIdx.x;
    int e = t >> 2, q = t & 3;
    const uint32_t* g; const int* src; const int* dst; const float* inv;
    if (e < Er) {
        g = d_gu; src = r_src; dst = r_dst; inv = d_invr;
    } else if ((e -= Er) < Edi) {
        g = d_gd; src = di_src; dst = di_dst; inv = d_invdi;
    } else return;
    int s = __ldg(&src[e]);
    int d = __ldg(&dst[e]);
    float sc = __ldg(&inv[d]);
    uint2 h = __ldg((const uint2*)&g[(size_t)s * 8 + q * 2]);
    float2 f0 = unpack_h2(h.x), f1 = unpack_h2(h.y);
    float4 v = make_float4(f0.x * sc, f0.y * sc, f1.x * sc, f1.y * sc);
    atomicAdd(&out[(size_t)d * 4 + q], v);
}

// ---------------- host launch ----------------
extern "C" void kernel_launch(void* const* d_in, const int* in_sizes, int n_in,
                              void* d_out, int out_size) {
    const float *x_u, *x_m, *x_d, *W_u, *b_u, *W_m, *b_m, *W_d, *b_d, *W_o, *b_o;
    const int *r_src, *r_dst, *rb_src, *rb_dst, *di_src, *di_dst, *db_src, *db_dst;
    int Er, Erb, Edi, Edb;

    if (in_sizes[3] == 128 * 128) {
        x_u = (const float*)d_in[0];  x_m = (const float*)d_in[1];  x_d = (const float*)d_in[2];
        W_u = (const float*)d_in[3];  b_u = (const float*)d_in[4];
        W_m = (const float*)d_in[5];  b_m = (const float*)d_in[6];
        W_d = (const float*)d_in[7];  b_d = (const float*)d_in[8];
        W_o = (const float*)d_in[9];  b_o = (const float*)d_in[10];
        r_src = (const int*)d_in[11]; r_dst = (const int*)d_in[12];
        rb_src = (const int*)d_in[13]; rb_dst = (const int*)d_in[14];
        di_src = (const int*)d_in[15]; di_dst = (const int*)d_in[16];
        db_src = (const int*)d_in[17]; db_dst = (const int*)d_in[18];
        Er = in_sizes[11]; Erb = in_sizes[13]; Edi = in_sizes[15]; Edb = in_sizes[17];
    } else {
        x_u = (const float*)d_in[0];  x_m = (const float*)d_in[1];  x_d = (const float*)d_in[2];
        r_src = (const int*)d_in[3];  r_dst = (const int*)d_in[4];
        rb_src = (const int*)d_in[5]; rb_dst = (const int*)d_in[6];
        di_src = (const int*)d_in[7]; di_dst = (const int*)d_in[8];
        db_src = (const int*)d_in[9]; db_dst = (const int*)d_in[10];
        W_u = (const float*)d_in[11]; b_u = (const float*)d_in[12];
        W_m = (const float*)d_in[13]; b_m = (const float*)d_in[14];
        W_d = (const float*)d_in[15]; b_d = (const float*)d_in[16];
        W_o = (const float*)d_in[17]; b_o = (const float*)d_in[18];
        Er = in_sizes[3]; Erb = in_sizes[5]; Edi = in_sizes[7]; Edb = in_sizes[9];
    }

    uint32_t *gu, *gm, *gd;
    cudaGetSymbolAddress((void**)&gu, d_gu);
    cudaGetSymbolAddress((void**)&gm, d_gm);
    cudaGetSymbolAddress((void**)&gd, d_gd);

    cudaFuncSetAttribute(gemm_all, cudaFuncAttributeMaxDynamicSharedMemorySize, SM_TOTAL);

    const int T = 256;
    const int Etot = Er + Edi + Erb + Edb;

    // 0) one persistent GEMM for all three node types (fp16 G output)
    gemm_all<<<GEMM_GRID, 256, SM_TOTAL>>>(
        (const float4*)x_u, (const float4*)x_m, (const float4*)x_d,
        (const float4*)W_u, (const float4*)W_m, (const float4*)W_d,
        b_u, b_m, b_d, W_o, gu, gm, gd);

    // 1) layer-1 fp16 raw-sum scatters + degree counting (2 threads/edge)
    scatter_l1_k<<<(Etot * 2 + T - 1) / T, T>>>(r_src, r_dst, Er, di_src, di_dst, Edi,
                                                rb_src, rb_dst, Erb, db_src, db_dst, Edb);
    // 2) update + movie output base + layer-2 scales + counter re-zero
    update_all_k<<<((NU + NM + ND) * 4 + T - 1) / T, T>>>((const float4*)b_o, (float4*)d_out);
    // 3) layer-2 scatters add directly into the output (4 threads/edge, fp32 REDs)
    scatter_l2_k<<<((Er + Edi) * 4 + T - 1) / T, T>>>(r_src, r_dst, Er, di_src, di_dst, Edi,
                                                      (float4*)d_out);
}